// round 1
// baseline (speedup 1.0000x reference)
#include <cuda_runtime.h>
#include <cuda_bf16.h>
#include <math.h>

#define Bz   4
#define LQ   1024
#define Cc   256
#define Hh   8
#define DH   32
#define Ll   4
#define Pp   4
#define DFF  1024
#define LSRC 21760
#define MROWS (Bz*LQ)        // 4096
#define VROWS (Bz*LSRC)      // 87040

// ---------------- scratch (static device globals; no runtime allocation) ----
__device__ float g_qk  [MROWS*Cc];
__device__ float g_q   [MROWS*Cc];
__device__ float g_k   [MROWS*Cc];
__device__ float g_v   [MROWS*Cc];
__device__ float g_attn[MROWS*Cc];
__device__ float g_tmp [MROWS*Cc];
__device__ float g_tgt1[MROWS*Cc];
__device__ float g_tgt2[MROWS*Cc];
__device__ float g_off [MROWS*Cc];
__device__ float g_aw  [MROWS*(Hh*Ll*Pp)];
__device__ float g_val [VROWS*Cc];
__device__ float g_ffn [MROWS*DFF];

// ---------------- elementwise add ------------------------------------------
__global__ void add_kernel(const float* __restrict__ a, const float* __restrict__ b,
                           float* __restrict__ y, int n)
{
    int i = blockIdx.x * 256 + threadIdx.x;
    if (i < n) y[i] = a[i] + b[i];
}

// ---------------- generic SGEMM: Y[M,N] = X[M,K] @ W[N,K]^T + bias ----------
// 64x64 tile, BK=16, 256 threads, 4x4 per-thread micro tile.
__global__ void gemm_kernel(const float* __restrict__ X, const float* __restrict__ W,
                            const float* __restrict__ bias, float* __restrict__ Y,
                            int M, int N, int K, int relu)
{
    __shared__ float Xs[16][64];
    __shared__ float Ws[16][64];

    const int t   = threadIdx.x;
    const int tx  = t & 15;          // col group
    const int ty  = t >> 4;          // row group
    const int m0  = blockIdx.y * 64;
    const int n0  = blockIdx.x * 64;

    const int lrow = t >> 2;         // 0..63
    const int kseg = (t & 3) * 4;    // 0,4,8,12

    float acc[4][4];
#pragma unroll
    for (int i = 0; i < 4; i++)
#pragma unroll
        for (int j = 0; j < 4; j++) acc[i][j] = 0.f;

    for (int k0 = 0; k0 < K; k0 += 16) {
        float4 xv = *(const float4*)&X[(size_t)(m0 + lrow) * K + k0 + kseg];
        float4 wv = *(const float4*)&W[(size_t)(n0 + lrow) * K + k0 + kseg];
        Xs[kseg + 0][lrow] = xv.x; Xs[kseg + 1][lrow] = xv.y;
        Xs[kseg + 2][lrow] = xv.z; Xs[kseg + 3][lrow] = xv.w;
        Ws[kseg + 0][lrow] = wv.x; Ws[kseg + 1][lrow] = wv.y;
        Ws[kseg + 2][lrow] = wv.z; Ws[kseg + 3][lrow] = wv.w;
        __syncthreads();
#pragma unroll
        for (int kk = 0; kk < 16; kk++) {
            float4 a = *(const float4*)&Xs[kk][ty * 4];
            float4 b = *(const float4*)&Ws[kk][tx * 4];
            float av[4] = {a.x, a.y, a.z, a.w};
            float bv[4] = {b.x, b.y, b.z, b.w};
#pragma unroll
            for (int i = 0; i < 4; i++)
#pragma unroll
                for (int j = 0; j < 4; j++) acc[i][j] += av[i] * bv[j];
        }
        __syncthreads();
    }

#pragma unroll
    for (int i = 0; i < 4; i++) {
        int mm = m0 + ty * 4 + i;
#pragma unroll
        for (int j = 0; j < 4; j++) {
            int nn = n0 + tx * 4 + j;
            float vv = acc[i][j] + bias[nn];
            if (relu) vv = fmaxf(vv, 0.f);
            Y[(size_t)mm * N + nn] = vv;
        }
    }
}

// ---------------- residual + LayerNorm (row = 256) --------------------------
__global__ void add_ln_kernel(const float* __restrict__ A, const float* __restrict__ Bv,
                              const float* __restrict__ g, const float* __restrict__ be,
                              float* __restrict__ Y)
{
    int row = blockIdx.x, t = threadIdx.x;
    float x = A[(size_t)row * Cc + t] + Bv[(size_t)row * Cc + t];
    float s = x, s2 = x * x;
#pragma unroll
    for (int o = 16; o > 0; o >>= 1) {
        s  += __shfl_xor_sync(0xffffffffu, s, o);
        s2 += __shfl_xor_sync(0xffffffffu, s2, o);
    }
    __shared__ float ss[8], ss2[8];
    int w = t >> 5;
    if ((t & 31) == 0) { ss[w] = s; ss2[w] = s2; }
    __syncthreads();
    s = 0.f; s2 = 0.f;
#pragma unroll
    for (int i = 0; i < 8; i++) { s += ss[i]; s2 += ss2[i]; }
    float mean = s * (1.f / Cc);
    float var  = s2 * (1.f / Cc) - mean * mean;
    float inv  = rsqrtf(var + 1e-5f);
    Y[(size_t)row * Cc + t] = (x - mean) * inv * g[t] + be[t];
}

// ---------------- MHA attention (flash style, warp per query) ---------------
// Q,K,V: (B*LQ, 256) with head h at cols [h*32, h*32+32)
__global__ void attn_kernel(const float* __restrict__ Q, const float* __restrict__ K,
                            const float* __restrict__ V, float* __restrict__ O)
{
    __shared__ float Ks[64][33];
    __shared__ float Vs[64][33];
    const int bh = blockIdx.y;
    const int b = bh >> 3, h = bh & 7;
    const int warp = threadIdx.x >> 5, lane = threadIdx.x & 31;
    const int q = blockIdx.x * 4 + warp;
    const size_t qrow = (size_t)(b * LQ + q) * Cc + h * DH;

    float qreg[32];
#pragma unroll
    for (int d = 0; d < 32; d++) qreg[d] = Q[qrow + d] * 0.17677669529663687f;

    float m = -1e30f, l = 0.f;
    float acc[32];
#pragma unroll
    for (int d = 0; d < 32; d++) acc[d] = 0.f;

    for (int c0 = 0; c0 < LQ; c0 += 64) {
        __syncthreads();
        for (int i = threadIdx.x; i < 64 * 32; i += 128) {
            int j = i >> 5, d = i & 31;
            size_t src = (size_t)(b * LQ + c0 + j) * Cc + h * DH + d;
            Ks[j][d] = K[src];
            Vs[j][d] = V[src];
        }
        __syncthreads();
#pragma unroll
        for (int tt = 0; tt < 2; tt++) {
            int j = lane + 32 * tt;
            float s = 0.f;
#pragma unroll
            for (int d = 0; d < 32; d++) s += qreg[d] * Ks[j][d];
            if (s > m) {
                float corr = __expf(m - s);
                l *= corr;
#pragma unroll
                for (int d = 0; d < 32; d++) acc[d] *= corr;
                m = s;
            }
            float p = __expf(s - m);
            l += p;
#pragma unroll
            for (int d = 0; d < 32; d++) acc[d] += p * Vs[j][d];
        }
    }
    // merge lanes
    float M = m;
#pragma unroll
    for (int o = 16; o > 0; o >>= 1) M = fmaxf(M, __shfl_xor_sync(0xffffffffu, M, o));
    float scale = __expf(m - M);
    float Ltot = l * scale;
#pragma unroll
    for (int o = 16; o > 0; o >>= 1) Ltot += __shfl_xor_sync(0xffffffffu, Ltot, o);
    float inv = 1.f / Ltot;
#pragma unroll
    for (int d = 0; d < 32; d++) {
        float v = acc[d] * scale;
#pragma unroll
        for (int o = 16; o > 0; o >>= 1) v += __shfl_xor_sync(0xffffffffu, v, o);
        if (lane == d) O[qrow + d] = v * inv;
    }
}

// ---------------- deformable sampling (warp per (b,q,h), lane = channel) ----
__global__ void deform_kernel(const float* __restrict__ val, const float* __restrict__ offs,
                              const float* __restrict__ awl, const float* __restrict__ ref,
                              float* __restrict__ out)
{
    const int gid  = blockIdx.x * 4 + (threadIdx.x >> 5);
    const int lane = threadIdx.x & 31;
    const int h   = gid & 7;
    const int row = gid >> 3;            // b*LQ + q
    const int b   = row >> 10;

    // softmax over 16 attention logits (redundant on all lanes; broadcast loads)
    float a[16];
    float mx = -1e30f;
#pragma unroll
    for (int i = 0; i < 16; i++) {
        a[i] = awl[(size_t)row * 128 + h * 16 + i];
        mx = fmaxf(mx, a[i]);
    }
    float ssum = 0.f;
#pragma unroll
    for (int i = 0; i < 16; i++) { a[i] = __expf(a[i] - mx); ssum += a[i]; }
    float invs = 1.f / ssum;

    const int starts[4] = {0, 16384, 20480, 21504};
    float acc = 0.f;
#pragma unroll
    for (int lvl = 0; lvl < 4; lvl++) {
        const int Wl = 128 >> lvl;
        const int Hl = 128 >> lvl;
        const int start = starts[lvl];
        float rx = ref[((size_t)row * 4 + lvl) * 2 + 0];
        float ry = ref[((size_t)row * 4 + lvl) * 2 + 1];
#pragma unroll
        for (int p = 0; p < 4; p++) {
            size_t obase = (size_t)row * 256 + (((h * 4 + lvl) * 4 + p) * 2);
            float ox = offs[obase + 0];
            float oy = offs[obase + 1];
            float x = rx * (float)Wl + ox - 0.5f;
            float y = ry * (float)Hl + oy - 0.5f;
            float xf = floorf(x), yf = floorf(y);
            int x0 = (int)xf, y0 = (int)yf;
            float wx1 = x - xf, wx0 = 1.f - wx1;
            float wy1 = y - yf, wy0 = 1.f - wy1;
            float aw = a[lvl * 4 + p] * invs;

            float w00 = wx0 * wy0 * aw, w10 = wx1 * wy0 * aw;
            float w01 = wx0 * wy1 * aw, w11 = wx1 * wy1 * aw;
#pragma unroll
            for (int c = 0; c < 4; c++) {
                int ix = x0 + (c & 1);
                int iy = y0 + (c >> 1);
                float w = (c == 0) ? w00 : (c == 1) ? w10 : (c == 2) ? w01 : w11;
                if (ix >= 0 && ix < Wl && iy >= 0 && iy < Hl) {
                    size_t idx = (size_t)(b * LSRC + start + iy * Wl + ix) * Cc + h * DH + lane;
                    acc += w * val[idx];
                }
            }
        }
    }
    out[(size_t)row * Cc + h * DH + lane] = acc;
}

// ---------------- launcher ---------------------------------------------------
extern "C" void kernel_launch(void* const* d_in, const int* in_sizes, int n_in,
                              void* d_out, int out_size)
{
    const float* tgt   = (const float*)d_in[0];
    const float* qpos  = (const float*)d_in[1];
    const float* refp  = (const float*)d_in[2];
    const float* src   = (const float*)d_in[3];
    const float* in_w  = (const float*)d_in[4];
    const float* in_b  = (const float*)d_in[5];
    const float* sa_w  = (const float*)d_in[6];
    const float* sa_b  = (const float*)d_in[7];
    const float* off_w = (const float*)d_in[8];
    const float* off_b = (const float*)d_in[9];
    const float* aw_w  = (const float*)d_in[10];
    const float* aw_b  = (const float*)d_in[11];
    const float* val_w = (const float*)d_in[12];
    const float* val_b = (const float*)d_in[13];
    const float* co_w  = (const float*)d_in[14];
    const float* co_b  = (const float*)d_in[15];
    const float* ln1_g = (const float*)d_in[16];
    const float* ln1_b = (const float*)d_in[17];
    const float* ln2_g = (const float*)d_in[18];
    const float* ln2_b = (const float*)d_in[19];
    const float* ln3_g = (const float*)d_in[20];
    const float* ln3_b = (const float*)d_in[21];
    const float* f1_w  = (const float*)d_in[22];
    const float* f1_b  = (const float*)d_in[23];
    const float* f2_w  = (const float*)d_in[24];
    const float* f2_b  = (const float*)d_in[25];
    float* out = (float*)d_out;

    float *qk, *q, *k, *v, *attn, *tmp, *t1, *t2, *off, *aw, *val, *ffn;
    cudaGetSymbolAddress((void**)&qk,   g_qk);
    cudaGetSymbolAddress((void**)&q,    g_q);
    cudaGetSymbolAddress((void**)&k,    g_k);
    cudaGetSymbolAddress((void**)&v,    g_v);
    cudaGetSymbolAddress((void**)&attn, g_attn);
    cudaGetSymbolAddress((void**)&tmp,  g_tmp);
    cudaGetSymbolAddress((void**)&t1,   g_tgt1);
    cudaGetSymbolAddress((void**)&t2,   g_tgt2);
    cudaGetSymbolAddress((void**)&off,  g_off);
    cudaGetSymbolAddress((void**)&aw,   g_aw);
    cudaGetSymbolAddress((void**)&val,  g_val);
    cudaGetSymbolAddress((void**)&ffn,  g_ffn);

    const int NTOT = MROWS * Cc;

    // 1) qk = tgt + query_pos
    add_kernel<<<(NTOT + 255) / 256, 256>>>(tgt, qpos, qk, NTOT);

    // 2) Q/K/V projections
    {
        dim3 grid(Cc / 64, MROWS / 64);
        gemm_kernel<<<grid, 256>>>(qk,  in_w,            in_b,            q, MROWS, Cc, Cc, 0);
        gemm_kernel<<<grid, 256>>>(qk,  in_w + 256*Cc,   in_b + 256,      k, MROWS, Cc, Cc, 0);
        gemm_kernel<<<grid, 256>>>(tgt, in_w + 512*Cc,   in_b + 512,      v, MROWS, Cc, Cc, 0);
    }

    // 3) attention
    {
        dim3 grid(LQ / 4, Bz * Hh);
        attn_kernel<<<grid, 128>>>(q, k, v, attn);
    }

    // 4) self-attn out proj + residual + LN(ln2) -> t1
    {
        dim3 grid(Cc / 64, MROWS / 64);
        gemm_kernel<<<grid, 256>>>(attn, sa_w, sa_b, tmp, MROWS, Cc, Cc, 0);
    }
    add_ln_kernel<<<MROWS, 256>>>(tgt, tmp, ln2_g, ln2_b, t1);

    // 5) query = t1 + query_pos (reuse qk)
    add_kernel<<<(NTOT + 255) / 256, 256>>>(t1, qpos, qk, NTOT);

    // 6) offsets, attention weights, value projection
    {
        dim3 grid(Cc / 64, MROWS / 64);
        gemm_kernel<<<grid, 256>>>(qk, off_w, off_b, off, MROWS, Cc, Cc, 0);
    }
    {
        dim3 grid(128 / 64, MROWS / 64);
        gemm_kernel<<<grid, 256>>>(qk, aw_w, aw_b, aw, MROWS, 128, Cc, 0);
    }
    {
        dim3 grid(Cc / 64, VROWS / 64);
        gemm_kernel<<<grid, 256>>>(src, val_w, val_b, val, VROWS, Cc, Cc, 0);
    }

    // 7) deformable sampling -> attn (reused)
    deform_kernel<<<(MROWS * Hh) / 4, 128>>>(val, off, aw, refp, attn);

    // 8) co proj + residual + LN(ln1) -> t2
    {
        dim3 grid(Cc / 64, MROWS / 64);
        gemm_kernel<<<grid, 256>>>(attn, co_w, co_b, tmp, MROWS, Cc, Cc, 0);
    }
    add_ln_kernel<<<MROWS, 256>>>(t1, tmp, ln1_g, ln1_b, t2);

    // 9) FFN + residual + LN(ln3) -> out
    {
        dim3 grid(DFF / 64, MROWS / 64);
        gemm_kernel<<<grid, 256>>>(t2, f1_w, f1_b, ffn, MROWS, DFF, Cc, 1);
    }
    {
        dim3 grid(Cc / 64, MROWS / 64);
        gemm_kernel<<<grid, 256>>>(ffn, f2_w, f2_b, tmp, MROWS, Cc, DFF, 0);
    }
    add_ln_kernel<<<MROWS, 256>>>(t2, tmp, ln3_g, ln3_b, out);
}

// round 3
// speedup vs baseline: 1.9033x; 1.9033x over previous
#include <cuda_runtime.h>
#include <cuda_bf16.h>
#include <math.h>

#define Bz   4
#define LQ   1024
#define Cc   256
#define Hh   8
#define DH   32
#define DFF  1024
#define LSRC 21760
#define MROWS (Bz*LQ)        // 4096
#define VROWS (Bz*LSRC)      // 87040

// ---------------- scratch (static device globals) ---------------------------
__device__ float g_qk  [MROWS*Cc];
__device__ float g_q   [MROWS*Cc];
__device__ float g_k   [MROWS*Cc];
__device__ float g_v   [MROWS*Cc];
__device__ float g_attn[MROWS*Cc];
__device__ float g_tmp [MROWS*Cc];
__device__ float g_tgt1[MROWS*Cc];
__device__ float g_tgt2[MROWS*Cc];
__device__ float g_off [MROWS*Cc];
__device__ float g_aw  [MROWS*128];
__device__ float g_val [VROWS*Cc];
__device__ float g_ffn [MROWS*DFF];

__device__ __forceinline__ unsigned f2tf32(float x) {
    unsigned r;
    asm("cvt.rna.tf32.f32 %0, %1;" : "=r"(r) : "f"(x));
    return r;
}

// ---------------- elementwise add ------------------------------------------
__global__ void add_kernel(const float* __restrict__ a, const float* __restrict__ b,
                           float* __restrict__ y, int n)
{
    int i = blockIdx.x * 256 + threadIdx.x;
    if (i < n) y[i] = a[i] + b[i];
}

// ---------------- tf32 tensor-core GEMM: Y[M,N] = X[M,K] @ W[N,K]^T + bias --
// 128x128x32 block tile, 256 threads (8 warps, 2x4), warp tile 64x32.
// Requires M%128==0, N%128==0, K%32==0.
#define GPAD 36
__global__ __launch_bounds__(256, 2)
void gemm_tc_kernel(const float* __restrict__ X, const float* __restrict__ W,
                    const float* __restrict__ bias, float* __restrict__ Y,
                    int M, int N, int K, int relu)
{
    __shared__ float Xs[128][GPAD];
    __shared__ float Ws[128][GPAD];

    const int t    = threadIdx.x;
    const int warp = t >> 5;
    const int lane = t & 31;
    const int g    = lane >> 2;      // 0..7
    const int tg   = lane & 3;       // 0..3
    const int warp_m = warp >> 2;    // 0..1
    const int warp_n = warp & 3;     // 0..3
    const int m0 = blockIdx.y * 128;
    const int n0 = blockIdx.x * 128;

    float c[4][4][4];
#pragma unroll
    for (int i = 0; i < 4; i++)
#pragma unroll
        for (int j = 0; j < 4; j++)
#pragma unroll
            for (int r = 0; r < 4; r++) c[i][j][r] = 0.f;

    for (int k0 = 0; k0 < K; k0 += 32) {
        // load 128x32 tiles of X and W
#pragma unroll
        for (int p = 0; p < 4; p++) {
            int idx = (p * 256 + t) * 4;
            int row = idx >> 5;
            int kk  = idx & 31;
            float4 xv = *(const float4*)&X[(size_t)(m0 + row) * K + k0 + kk];
            float4 wv = *(const float4*)&W[(size_t)(n0 + row) * K + k0 + kk];
            *(float4*)&Xs[row][kk] = xv;
            *(float4*)&Ws[row][kk] = wv;
        }
        __syncthreads();

#pragma unroll
        for (int ks = 0; ks < 4; ks++) {
            const int kk = ks * 8;
            unsigned a[4][4], b[4][2];
#pragma unroll
            for (int mt = 0; mt < 4; mt++) {
                int rb = warp_m * 64 + mt * 16;
                a[mt][0] = f2tf32(Xs[rb + g    ][kk + tg    ]);
                a[mt][1] = f2tf32(Xs[rb + g + 8][kk + tg    ]);
                a[mt][2] = f2tf32(Xs[rb + g    ][kk + tg + 4]);
                a[mt][3] = f2tf32(Xs[rb + g + 8][kk + tg + 4]);
            }
#pragma unroll
            for (int nt = 0; nt < 4; nt++) {
                int nb = warp_n * 32 + nt * 8 + g;
                b[nt][0] = f2tf32(Ws[nb][kk + tg    ]);
                b[nt][1] = f2tf32(Ws[nb][kk + tg + 4]);
            }
#pragma unroll
            for (int mt = 0; mt < 4; mt++)
#pragma unroll
                for (int nt = 0; nt < 4; nt++) {
                    asm volatile(
                        "mma.sync.aligned.m16n8k8.row.col.f32.tf32.tf32.f32 "
                        "{%0,%1,%2,%3}, {%4,%5,%6,%7}, {%8,%9}, {%0,%1,%2,%3};"
                        : "+f"(c[mt][nt][0]), "+f"(c[mt][nt][1]),
                          "+f"(c[mt][nt][2]), "+f"(c[mt][nt][3])
                        : "r"(a[mt][0]), "r"(a[mt][1]), "r"(a[mt][2]), "r"(a[mt][3]),
                          "r"(b[nt][0]), "r"(b[nt][1]));
                }
        }
        __syncthreads();
    }

    // store: C[row][col]; row = m0 + warp_m*64 + mt*16 + g (+8 for regs 2,3)
    //        col = n0 + warp_n*32 + nt*8 + 2*tg (+1 for odd reg)
#pragma unroll
    for (int mt = 0; mt < 4; mt++) {
#pragma unroll
        for (int nt = 0; nt < 4; nt++) {
            int col = n0 + warp_n * 32 + nt * 8 + 2 * tg;
            float b0 = bias[col], b1 = bias[col + 1];
            int r0 = m0 + warp_m * 64 + mt * 16 + g;
            float v0 = c[mt][nt][0] + b0;
            float v1 = c[mt][nt][1] + b1;
            float v2 = c[mt][nt][2] + b0;
            float v3 = c[mt][nt][3] + b1;
            if (relu) {
                v0 = fmaxf(v0, 0.f); v1 = fmaxf(v1, 0.f);
                v2 = fmaxf(v2, 0.f); v3 = fmaxf(v3, 0.f);
            }
            Y[(size_t)r0 * N + col]           = v0;
            Y[(size_t)r0 * N + col + 1]       = v1;
            Y[(size_t)(r0 + 8) * N + col]     = v2;
            Y[(size_t)(r0 + 8) * N + col + 1] = v3;
        }
    }
}

// ---------------- residual + LayerNorm (row = 256) --------------------------
__global__ void add_ln_kernel(const float* __restrict__ A, const float* __restrict__ Bv,
                              const float* __restrict__ g, const float* __restrict__ be,
                              float* __restrict__ Y)
{
    int row = blockIdx.x, t = threadIdx.x;
    float x = A[(size_t)row * Cc + t] + Bv[(size_t)row * Cc + t];
    float s = x, s2 = x * x;
#pragma unroll
    for (int o = 16; o > 0; o >>= 1) {
        s  += __shfl_xor_sync(0xffffffffu, s, o);
        s2 += __shfl_xor_sync(0xffffffffu, s2, o);
    }
    __shared__ float ss[8], ss2[8];
    int w = t >> 5;
    if ((t & 31) == 0) { ss[w] = s; ss2[w] = s2; }
    __syncthreads();
    s = 0.f; s2 = 0.f;
#pragma unroll
    for (int i = 0; i < 8; i++) { s += ss[i]; s2 += ss2[i]; }
    float mean = s * (1.f / Cc);
    float var  = s2 * (1.f / Cc) - mean * mean;
    float inv  = rsqrtf(var + 1e-5f);
    Y[(size_t)row * Cc + t] = (x - mean) * inv * g[t] + be[t];
}

// ---------------- MHA attention (flash style, warp per query) ---------------
__global__ void attn_kernel(const float* __restrict__ Q, const float* __restrict__ K,
                            const float* __restrict__ V, float* __restrict__ O)
{
    __shared__ float Ks[64][33];
    __shared__ float Vs[64][33];
    const int bh = blockIdx.y;
    const int b = bh >> 3, h = bh & 7;
    const int warp = threadIdx.x >> 5, lane = threadIdx.x & 31;
    const int q = blockIdx.x * 4 + warp;
    const size_t qrow = (size_t)(b * LQ + q) * Cc + h * DH;

    float qreg[32];
#pragma unroll
    for (int d = 0; d < 32; d++) qreg[d] = Q[qrow + d] * 0.17677669529663687f;

    float m = -1e30f, l = 0.f;
    float acc[32];
#pragma unroll
    for (int d = 0; d < 32; d++) acc[d] = 0.f;

    for (int c0 = 0; c0 < LQ; c0 += 64) {
        __syncthreads();
        for (int i = threadIdx.x; i < 64 * 32; i += 128) {
            int j = i >> 5, d = i & 31;
            size_t src = (size_t)(b * LQ + c0 + j) * Cc + h * DH + d;
            Ks[j][d] = K[src];
            Vs[j][d] = V[src];
        }
        __syncthreads();
#pragma unroll
        for (int tt = 0; tt < 2; tt++) {
            int j = lane + 32 * tt;
            float s = 0.f;
#pragma unroll
            for (int d = 0; d < 32; d++) s += qreg[d] * Ks[j][d];
            if (s > m) {
                float corr = __expf(m - s);
                l *= corr;
#pragma unroll
                for (int d = 0; d < 32; d++) acc[d] *= corr;
                m = s;
            }
            float p = __expf(s - m);
            l += p;
#pragma unroll
            for (int d = 0; d < 32; d++) acc[d] += p * Vs[j][d];
        }
    }
    float M = m;
#pragma unroll
    for (int o = 16; o > 0; o >>= 1) M = fmaxf(M, __shfl_xor_sync(0xffffffffu, M, o));
    float scale = __expf(m - M);
    float Ltot = l * scale;
#pragma unroll
    for (int o = 16; o > 0; o >>= 1) Ltot += __shfl_xor_sync(0xffffffffu, Ltot, o);
    float inv = 1.f / Ltot;
#pragma unroll
    for (int d = 0; d < 32; d++) {
        float v = acc[d] * scale;
#pragma unroll
        for (int o = 16; o > 0; o >>= 1) v += __shfl_xor_sync(0xffffffffu, v, o);
        if (lane == d) O[qrow + d] = v * inv;
    }
}

// ---------------- deformable sampling (warp per (b,q,h), lane = channel) ----
__global__ void deform_kernel(const float* __restrict__ val, const float* __restrict__ offs,
                              const float* __restrict__ awl, const float* __restrict__ ref,
                              float* __restrict__ out)
{
    const int gid  = blockIdx.x * 4 + (threadIdx.x >> 5);
    const int lane = threadIdx.x & 31;
    const int h   = gid & 7;
    const int row = gid >> 3;
    const int b   = row >> 10;

    float a[16];
    float mx = -1e30f;
#pragma unroll
    for (int i = 0; i < 16; i++) {
        a[i] = awl[(size_t)row * 128 + h * 16 + i];
        mx = fmaxf(mx, a[i]);
    }
    float ssum = 0.f;
#pragma unroll
    for (int i = 0; i < 16; i++) { a[i] = __expf(a[i] - mx); ssum += a[i]; }
    float invs = 1.f / ssum;

    const int starts[4] = {0, 16384, 20480, 21504};
    float acc = 0.f;
#pragma unroll
    for (int lvl = 0; lvl < 4; lvl++) {
        const int Wl = 128 >> lvl;
        const int Hl = 128 >> lvl;
        const int start = starts[lvl];
        float rx = ref[((size_t)row * 4 + lvl) * 2 + 0];
        float ry = ref[((size_t)row * 4 + lvl) * 2 + 1];
#pragma unroll
        for (int p = 0; p < 4; p++) {
            size_t obase = (size_t)row * 256 + (((h * 4 + lvl) * 4 + p) * 2);
            float ox = offs[obase + 0];
            float oy = offs[obase + 1];
            float x = rx * (float)Wl + ox - 0.5f;
            float y = ry * (float)Hl + oy - 0.5f;
            float xf = floorf(x), yf = floorf(y);
            int x0 = (int)xf, y0 = (int)yf;
            float wx1 = x - xf, wx0 = 1.f - wx1;
            float wy1 = y - yf, wy0 = 1.f - wy1;
            float aw = a[lvl * 4 + p] * invs;

            float w00 = wx0 * wy0 * aw, w10 = wx1 * wy0 * aw;
            float w01 = wx0 * wy1 * aw, w11 = wx1 * wy1 * aw;
#pragma unroll
            for (int cidx = 0; cidx < 4; cidx++) {
                int ix = x0 + (cidx & 1);
                int iy = y0 + (cidx >> 1);
                float w = (cidx == 0) ? w00 : (cidx == 1) ? w10 : (cidx == 2) ? w01 : w11;
                if (ix >= 0 && ix < Wl && iy >= 0 && iy < Hl) {
                    size_t idx = (size_t)(b * LSRC + start + iy * Wl + ix) * Cc + h * DH + lane;
                    acc += w * val[idx];
                }
            }
        }
    }
    out[(size_t)row * Cc + h * DH + lane] = acc;
}

// ---------------- launcher ---------------------------------------------------
extern "C" void kernel_launch(void* const* d_in, const int* in_sizes, int n_in,
                              void* d_out, int out_size)
{
    const float* tgt   = (const float*)d_in[0];
    const float* qpos  = (const float*)d_in[1];
    const float* refp  = (const float*)d_in[2];
    const float* src   = (const float*)d_in[3];
    const float* in_w  = (const float*)d_in[4];
    const float* in_b  = (const float*)d_in[5];
    const float* sa_w  = (const float*)d_in[6];
    const float* sa_b  = (const float*)d_in[7];
    const float* off_w = (const float*)d_in[8];
    const float* off_b = (const float*)d_in[9];
    const float* aw_w  = (const float*)d_in[10];
    const float* aw_b  = (const float*)d_in[11];
    const float* val_w = (const float*)d_in[12];
    const float* val_b = (const float*)d_in[13];
    const float* co_w  = (const float*)d_in[14];
    const float* co_b  = (const float*)d_in[15];
    const float* ln1_g = (const float*)d_in[16];
    const float* ln1_b = (const float*)d_in[17];
    const float* ln2_g = (const float*)d_in[18];
    const float* ln2_b = (const float*)d_in[19];
    const float* ln3_g = (const float*)d_in[20];
    const float* ln3_b = (const float*)d_in[21];
    const float* f1_w  = (const float*)d_in[22];
    const float* f1_b  = (const float*)d_in[23];
    const float* f2_w  = (const float*)d_in[24];
    const float* f2_b  = (const float*)d_in[25];
    float* out = (float*)d_out;

    float *qk, *q, *k, *v, *attn, *tmp, *t1, *t2, *off, *aw, *val, *ffn;
    cudaGetSymbolAddress((void**)&qk,   g_qk);
    cudaGetSymbolAddress((void**)&q,    g_q);
    cudaGetSymbolAddress((void**)&k,    g_k);
    cudaGetSymbolAddress((void**)&v,    g_v);
    cudaGetSymbolAddress((void**)&attn, g_attn);
    cudaGetSymbolAddress((void**)&tmp,  g_tmp);
    cudaGetSymbolAddress((void**)&t1,   g_tgt1);
    cudaGetSymbolAddress((void**)&t2,   g_tgt2);
    cudaGetSymbolAddress((void**)&off,  g_off);
    cudaGetSymbolAddress((void**)&aw,   g_aw);
    cudaGetSymbolAddress((void**)&val,  g_val);
    cudaGetSymbolAddress((void**)&ffn,  g_ffn);

    const int NTOT = MROWS * Cc;

    // 1) qk = tgt + query_pos
    add_kernel<<<(NTOT + 255) / 256, 256>>>(tgt, qpos, qk, NTOT);

    // 2) Q/K/V projections
    {
        dim3 grid(Cc / 128, MROWS / 128);
        gemm_tc_kernel<<<grid, 256>>>(qk,  in_w,          in_b,       q, MROWS, Cc, Cc, 0);
        gemm_tc_kernel<<<grid, 256>>>(qk,  in_w + 256*Cc, in_b + 256, k, MROWS, Cc, Cc, 0);
        gemm_tc_kernel<<<grid, 256>>>(tgt, in_w + 512*Cc, in_b + 512, v, MROWS, Cc, Cc, 0);
    }

    // 3) attention
    {
        dim3 grid(LQ / 4, Bz * Hh);
        attn_kernel<<<grid, 128>>>(q, k, v, attn);
    }

    // 4) self-attn out proj + residual + LN(ln2) -> t1
    {
        dim3 grid(Cc / 128, MROWS / 128);
        gemm_tc_kernel<<<grid, 256>>>(attn, sa_w, sa_b, tmp, MROWS, Cc, Cc, 0);
    }
    add_ln_kernel<<<MROWS, 256>>>(tgt, tmp, ln2_g, ln2_b, t1);

    // 5) query = t1 + query_pos
    add_kernel<<<(NTOT + 255) / 256, 256>>>(t1, qpos, qk, NTOT);

    // 6) offsets, attention weights, value projection
    {
        dim3 grid(Cc / 128, MROWS / 128);
        gemm_tc_kernel<<<grid, 256>>>(qk, off_w, off_b, off, MROWS, Cc, Cc, 0);
    }
    {
        dim3 grid(1, MROWS / 128);
        gemm_tc_kernel<<<grid, 256>>>(qk, aw_w, aw_b, aw, MROWS, 128, Cc, 0);
    }
    {
        dim3 grid(Cc / 128, VROWS / 128);
        gemm_tc_kernel<<<grid, 256>>>(src, val_w, val_b, val, VROWS, Cc, Cc, 0);
    }

    // 7) deformable sampling
    deform_kernel<<<(MROWS * Hh) / 4, 128>>>(val, off, aw, refp, attn);

    // 8) co proj + residual + LN(ln1) -> t2
    {
        dim3 grid(Cc / 128, MROWS / 128);
        gemm_tc_kernel<<<grid, 256>>>(attn, co_w, co_b, tmp, MROWS, Cc, Cc, 0);
    }
    add_ln_kernel<<<MROWS, 256>>>(t1, tmp, ln1_g, ln1_b, t2);

    // 9) FFN + residual + LN(ln3) -> out
    {
        dim3 grid(DFF / 128, MROWS / 128);
        gemm_tc_kernel<<<grid, 256>>>(t2, f1_w, f1_b, ffn, MROWS, DFF, Cc, 1);
    }
    {
        dim3 grid(Cc / 128, MROWS / 128);
        gemm_tc_kernel<<<grid, 256>>>(ffn, f2_w, f2_b, tmp, MROWS, Cc, DFF, 0);
    }
    add_ln_kernel<<<MROWS, 256>>>(t2, tmp, ln3_g, ln3_b, out);
}

// round 4
// speedup vs baseline: 1.9374x; 1.0179x over previous
#include <cuda_runtime.h>
#include <cuda_bf16.h>
#include <math.h>

#define Bz   4
#define LQ   1024
#define Cc   256
#define Hh   8
#define DH   32
#define DFF  1024
#define LSRC 21760
#define MROWS (Bz*LQ)        // 4096
#define VROWS (Bz*LSRC)      // 87040

// ---------------- scratch (static device globals) ---------------------------
__device__ float g_qk  [MROWS*Cc];
__device__ float g_q   [MROWS*Cc];
__device__ float g_k   [MROWS*Cc];
__device__ float g_v   [MROWS*Cc];
__device__ float g_attn[MROWS*Cc];
__device__ float g_tmp [MROWS*Cc];
__device__ float g_tgt1[MROWS*Cc];
__device__ float g_tgt2[MROWS*Cc];
__device__ float g_off [MROWS*Cc];
__device__ float g_aw  [MROWS*128];
__device__ float g_val [VROWS*Cc];
__device__ float g_ffn [MROWS*DFF];

__device__ __forceinline__ unsigned f2tf32(float x) {
    unsigned r;
    asm("cvt.rna.tf32.f32 %0, %1;" : "=r"(r) : "f"(x));
    return r;
}

// ---------------- elementwise add ------------------------------------------
__global__ void add_kernel(const float* __restrict__ a, const float* __restrict__ b,
                           float* __restrict__ y, int n)
{
    int i = blockIdx.x * 256 + threadIdx.x;
    if (i < n) y[i] = a[i] + b[i];
}

// ---------------- tf32 tensor-core GEMM, cp.async double-buffered -----------
// Y[M,N] = X[M,K] @ W[N,K]^T + bias ; 128x128x32 tile, 256 thr, warp tile 64x32
// Requires M%128==0, N%128==0, K%32==0.
#define GP 36                 // smem row pitch (floats): conflict-free + 16B aligned
#define TILE_F (128*GP)       // floats per matrix per stage
#define STAGE_F (2*TILE_F)    // X + W
#define GEMM_SMEM_BYTES (2*STAGE_F*4)

__global__ __launch_bounds__(256, 2)
void gemm_tc_kernel(const float* __restrict__ X, const float* __restrict__ W,
                    const float* __restrict__ bias, float* __restrict__ Y,
                    int M, int N, int K, int relu)
{
    extern __shared__ float smem[];

    const int t    = threadIdx.x;
    const int warp = t >> 5;
    const int lane = t & 31;
    const int g    = lane >> 2;
    const int tg   = lane & 3;
    const int warp_m = warp >> 2;
    const int warp_n = warp & 3;
    const int m0 = blockIdx.y * 128;
    const int n0 = blockIdx.x * 128;

    const int lrow = t >> 1;               // 0..127 : two threads per row
    const int lcol = (t & 1) * 16;         // 0 or 16

    float c[4][4][4];
#pragma unroll
    for (int i = 0; i < 4; i++)
#pragma unroll
        for (int j = 0; j < 4; j++)
#pragma unroll
            for (int r = 0; r < 4; r++) c[i][j][r] = 0.f;

    const int NS = K >> 5;

    // prefetch: copy 128x32 fp32 tiles of X and W into stage buffer via cp.async
    auto prefetch = [&](int s, int buf) {
        const int k0 = s << 5;
        float* xs = smem + buf * STAGE_F;
        float* ws = xs + TILE_F;
        const float* gx = &X[(size_t)(m0 + lrow) * K + k0 + lcol];
        const float* gw = &W[(size_t)(n0 + lrow) * K + k0 + lcol];
        unsigned sx = (unsigned)__cvta_generic_to_shared(&xs[lrow * GP + lcol]);
        unsigned sw = (unsigned)__cvta_generic_to_shared(&ws[lrow * GP + lcol]);
#pragma unroll
        for (int q = 0; q < 4; q++) {
            asm volatile("cp.async.cg.shared.global [%0], [%1], 16;\n"
                         :: "r"(sx + q * 16), "l"(gx + q * 4));
            asm volatile("cp.async.cg.shared.global [%0], [%1], 16;\n"
                         :: "r"(sw + q * 16), "l"(gw + q * 4));
        }
        asm volatile("cp.async.commit_group;\n");
    };

    prefetch(0, 0);

    for (int s = 0; s < NS; s++) {
        const int buf = s & 1;
        if (s + 1 < NS) {
            prefetch(s + 1, buf ^ 1);
            asm volatile("cp.async.wait_group 1;\n");
        } else {
            asm volatile("cp.async.wait_group 0;\n");
        }
        __syncthreads();

        const float* xs = smem + buf * STAGE_F;
        const float* ws = xs + TILE_F;

#pragma unroll
        for (int ks = 0; ks < 4; ks++) {
            const int kk = ks * 8;
            unsigned a[4][4], b[4][2];
#pragma unroll
            for (int mt = 0; mt < 4; mt++) {
                int rb = warp_m * 64 + mt * 16;
                a[mt][0] = f2tf32(xs[(rb + g    ) * GP + kk + tg    ]);
                a[mt][1] = f2tf32(xs[(rb + g + 8) * GP + kk + tg    ]);
                a[mt][2] = f2tf32(xs[(rb + g    ) * GP + kk + tg + 4]);
                a[mt][3] = f2tf32(xs[(rb + g + 8) * GP + kk + tg + 4]);
            }
#pragma unroll
            for (int nt = 0; nt < 4; nt++) {
                int nb = warp_n * 32 + nt * 8 + g;
                b[nt][0] = f2tf32(ws[nb * GP + kk + tg    ]);
                b[nt][1] = f2tf32(ws[nb * GP + kk + tg + 4]);
            }
#pragma unroll
            for (int mt = 0; mt < 4; mt++)
#pragma unroll
                for (int nt = 0; nt < 4; nt++) {
                    asm volatile(
                        "mma.sync.aligned.m16n8k8.row.col.f32.tf32.tf32.f32 "
                        "{%0,%1,%2,%3}, {%4,%5,%6,%7}, {%8,%9}, {%0,%1,%2,%3};"
                        : "+f"(c[mt][nt][0]), "+f"(c[mt][nt][1]),
                          "+f"(c[mt][nt][2]), "+f"(c[mt][nt][3])
                        : "r"(a[mt][0]), "r"(a[mt][1]), "r"(a[mt][2]), "r"(a[mt][3]),
                          "r"(b[nt][0]), "r"(b[nt][1]));
                }
        }
        __syncthreads();
    }

#pragma unroll
    for (int mt = 0; mt < 4; mt++) {
#pragma unroll
        for (int nt = 0; nt < 4; nt++) {
            int col = n0 + warp_n * 32 + nt * 8 + 2 * tg;
            float b0 = bias[col], b1 = bias[col + 1];
            int r0 = m0 + warp_m * 64 + mt * 16 + g;
            float v0 = c[mt][nt][0] + b0;
            float v1 = c[mt][nt][1] + b1;
            float v2 = c[mt][nt][2] + b0;
            float v3 = c[mt][nt][3] + b1;
            if (relu) {
                v0 = fmaxf(v0, 0.f); v1 = fmaxf(v1, 0.f);
                v2 = fmaxf(v2, 0.f); v3 = fmaxf(v3, 0.f);
            }
            Y[(size_t)r0 * N + col]           = v0;
            Y[(size_t)r0 * N + col + 1]       = v1;
            Y[(size_t)(r0 + 8) * N + col]     = v2;
            Y[(size_t)(r0 + 8) * N + col + 1] = v3;
        }
    }
}

// ---------------- residual + LayerNorm (row = 256) --------------------------
__global__ void add_ln_kernel(const float* __restrict__ A, const float* __restrict__ Bv,
                              const float* __restrict__ g, const float* __restrict__ be,
                              float* __restrict__ Y)
{
    int row = blockIdx.x, t = threadIdx.x;
    float x = A[(size_t)row * Cc + t] + Bv[(size_t)row * Cc + t];
    float s = x, s2 = x * x;
#pragma unroll
    for (int o = 16; o > 0; o >>= 1) {
        s  += __shfl_xor_sync(0xffffffffu, s, o);
        s2 += __shfl_xor_sync(0xffffffffu, s2, o);
    }
    __shared__ float ss[8], ss2[8];
    int w = t >> 5;
    if ((t & 31) == 0) { ss[w] = s; ss2[w] = s2; }
    __syncthreads();
    s = 0.f; s2 = 0.f;
#pragma unroll
    for (int i = 0; i < 8; i++) { s += ss[i]; s2 += ss2[i]; }
    float mean = s * (1.f / Cc);
    float var  = s2 * (1.f / Cc) - mean * mean;
    float inv  = rsqrtf(var + 1e-5f);
    Y[(size_t)row * Cc + t] = (x - mean) * inv * g[t] + be[t];
}

// ---------------- MHA attention (flash style, warp per query) ---------------
__global__ void attn_kernel(const float* __restrict__ Q, const float* __restrict__ K,
                            const float* __restrict__ V, float* __restrict__ O)
{
    __shared__ float Ks[64][33];
    __shared__ float Vs[64][33];
    const int bh = blockIdx.y;
    const int b = bh >> 3, h = bh & 7;
    const int warp = threadIdx.x >> 5, lane = threadIdx.x & 31;
    const int q = blockIdx.x * 4 + warp;
    const size_t qrow = (size_t)(b * LQ + q) * Cc + h * DH;

    float qreg[32];
#pragma unroll
    for (int d = 0; d < 32; d++) qreg[d] = Q[qrow + d] * 0.17677669529663687f;

    float m = -1e30f, l = 0.f;
    float acc[32];
#pragma unroll
    for (int d = 0; d < 32; d++) acc[d] = 0.f;

    for (int c0 = 0; c0 < LQ; c0 += 64) {
        __syncthreads();
        for (int i = threadIdx.x; i < 64 * 32; i += 128) {
            int j = i >> 5, d = i & 31;
            size_t src = (size_t)(b * LQ + c0 + j) * Cc + h * DH + d;
            Ks[j][d] = K[src];
            Vs[j][d] = V[src];
        }
        __syncthreads();
#pragma unroll
        for (int tt = 0; tt < 2; tt++) {
            int j = lane + 32 * tt;
            float s = 0.f;
#pragma unroll
            for (int d = 0; d < 32; d++) s += qreg[d] * Ks[j][d];
            if (s > m) {
                float corr = __expf(m - s);
                l *= corr;
#pragma unroll
                for (int d = 0; d < 32; d++) acc[d] *= corr;
                m = s;
            }
            float p = __expf(s - m);
            l += p;
#pragma unroll
            for (int d = 0; d < 32; d++) acc[d] += p * Vs[j][d];
        }
    }
    float M = m;
#pragma unroll
    for (int o = 16; o > 0; o >>= 1) M = fmaxf(M, __shfl_xor_sync(0xffffffffu, M, o));
    float scale = __expf(m - M);
    float Ltot = l * scale;
#pragma unroll
    for (int o = 16; o > 0; o >>= 1) Ltot += __shfl_xor_sync(0xffffffffu, Ltot, o);
    float inv = 1.f / Ltot;
#pragma unroll
    for (int d = 0; d < 32; d++) {
        float v = acc[d] * scale;
#pragma unroll
        for (int o = 16; o > 0; o >>= 1) v += __shfl_xor_sync(0xffffffffu, v, o);
        if (lane == d) O[qrow + d] = v * inv;
    }
}

// ---------------- deformable sampling (warp per (b,q,h), lane = channel) ----
__global__ void deform_kernel(const float* __restrict__ val, const float* __restrict__ offs,
                              const float* __restrict__ awl, const float* __restrict__ ref,
                              float* __restrict__ out)
{
    const int gid  = blockIdx.x * 4 + (threadIdx.x >> 5);
    const int lane = threadIdx.x & 31;
    const int h   = gid & 7;
    const int row = gid >> 3;
    const int b   = row >> 10;

    float a[16];
    float mx = -1e30f;
#pragma unroll
    for (int i = 0; i < 16; i++) {
        a[i] = awl[(size_t)row * 128 + h * 16 + i];
        mx = fmaxf(mx, a[i]);
    }
    float ssum = 0.f;
#pragma unroll
    for (int i = 0; i < 16; i++) { a[i] = __expf(a[i] - mx); ssum += a[i]; }
    float invs = 1.f / ssum;

    const int starts[4] = {0, 16384, 20480, 21504};
    float acc = 0.f;
#pragma unroll
    for (int lvl = 0; lvl < 4; lvl++) {
        const int Wl = 128 >> lvl;
        const int Hl = 128 >> lvl;
        const int start = starts[lvl];
        float rx = ref[((size_t)row * 4 + lvl) * 2 + 0];
        float ry = ref[((size_t)row * 4 + lvl) * 2 + 1];
#pragma unroll
        for (int p = 0; p < 4; p++) {
            size_t obase = (size_t)row * 256 + (((h * 4 + lvl) * 4 + p) * 2);
            float ox = offs[obase + 0];
            float oy = offs[obase + 1];
            float x = rx * (float)Wl + ox - 0.5f;
            float y = ry * (float)Hl + oy - 0.5f;
            float xf = floorf(x), yf = floorf(y);
            int x0 = (int)xf, y0 = (int)yf;
            float wx1 = x - xf, wx0 = 1.f - wx1;
            float wy1 = y - yf, wy0 = 1.f - wy1;
            float aw = a[lvl * 4 + p] * invs;

            float w00 = wx0 * wy0 * aw, w10 = wx1 * wy0 * aw;
            float w01 = wx0 * wy1 * aw, w11 = wx1 * wy1 * aw;
#pragma unroll
            for (int cidx = 0; cidx < 4; cidx++) {
                int ix = x0 + (cidx & 1);
                int iy = y0 + (cidx >> 1);
                float w = (cidx == 0) ? w00 : (cidx == 1) ? w10 : (cidx == 2) ? w01 : w11;
                if (ix >= 0 && ix < Wl && iy >= 0 && iy < Hl) {
                    size_t idx = (size_t)(b * LSRC + start + iy * Wl + ix) * Cc + h * DH + lane;
                    acc += w * val[idx];
                }
            }
        }
    }
    out[(size_t)row * Cc + h * DH + lane] = acc;
}

// ---------------- launcher ---------------------------------------------------
extern "C" void kernel_launch(void* const* d_in, const int* in_sizes, int n_in,
                              void* d_out, int out_size)
{
    const float* tgt   = (const float*)d_in[0];
    const float* qpos  = (const float*)d_in[1];
    const float* refp  = (const float*)d_in[2];
    const float* src   = (const float*)d_in[3];
    const float* in_w  = (const float*)d_in[4];
    const float* in_b  = (const float*)d_in[5];
    const float* sa_w  = (const float*)d_in[6];
    const float* sa_b  = (const float*)d_in[7];
    const float* off_w = (const float*)d_in[8];
    const float* off_b = (const float*)d_in[9];
    const float* aw_w  = (const float*)d_in[10];
    const float* aw_b  = (const float*)d_in[11];
    const float* val_w = (const float*)d_in[12];
    const float* val_b = (const float*)d_in[13];
    const float* co_w  = (const float*)d_in[14];
    const float* co_b  = (const float*)d_in[15];
    const float* ln1_g = (const float*)d_in[16];
    const float* ln1_b = (const float*)d_in[17];
    const float* ln2_g = (const float*)d_in[18];
    const float* ln2_b = (const float*)d_in[19];
    const float* ln3_g = (const float*)d_in[20];
    const float* ln3_b = (const float*)d_in[21];
    const float* f1_w  = (const float*)d_in[22];
    const float* f1_b  = (const float*)d_in[23];
    const float* f2_w  = (const float*)d_in[24];
    const float* f2_b  = (const float*)d_in[25];
    float* out = (float*)d_out;

    float *qk, *q, *k, *v, *attn, *tmp, *t1, *t2, *off, *aw, *val, *ffn;
    cudaGetSymbolAddress((void**)&qk,   g_qk);
    cudaGetSymbolAddress((void**)&q,    g_q);
    cudaGetSymbolAddress((void**)&k,    g_k);
    cudaGetSymbolAddress((void**)&v,    g_v);
    cudaGetSymbolAddress((void**)&attn, g_attn);
    cudaGetSymbolAddress((void**)&tmp,  g_tmp);
    cudaGetSymbolAddress((void**)&t1,   g_tgt1);
    cudaGetSymbolAddress((void**)&t2,   g_tgt2);
    cudaGetSymbolAddress((void**)&off,  g_off);
    cudaGetSymbolAddress((void**)&aw,   g_aw);
    cudaGetSymbolAddress((void**)&val,  g_val);
    cudaGetSymbolAddress((void**)&ffn,  g_ffn);

    static int smem_set = 0;
    if (!smem_set) {
        cudaFuncSetAttribute(gemm_tc_kernel,
                             cudaFuncAttributeMaxDynamicSharedMemorySize,
                             GEMM_SMEM_BYTES);
        smem_set = 1;
    }

    const int NTOT = MROWS * Cc;
    const int SB = GEMM_SMEM_BYTES;

    // 1) qk = tgt + query_pos
    add_kernel<<<(NTOT + 255) / 256, 256>>>(tgt, qpos, qk, NTOT);

    // 2) Q/K/V projections
    {
        dim3 grid(Cc / 128, MROWS / 128);
        gemm_tc_kernel<<<grid, 256, SB>>>(qk,  in_w,          in_b,       q, MROWS, Cc, Cc, 0);
        gemm_tc_kernel<<<grid, 256, SB>>>(qk,  in_w + 256*Cc, in_b + 256, k, MROWS, Cc, Cc, 0);
        gemm_tc_kernel<<<grid, 256, SB>>>(tgt, in_w + 512*Cc, in_b + 512, v, MROWS, Cc, Cc, 0);
    }

    // 3) attention
    {
        dim3 grid(LQ / 4, Bz * Hh);
        attn_kernel<<<grid, 128>>>(q, k, v, attn);
    }

    // 4) self-attn out proj + residual + LN(ln2) -> t1
    {
        dim3 grid(Cc / 128, MROWS / 128);
        gemm_tc_kernel<<<grid, 256, SB>>>(attn, sa_w, sa_b, tmp, MROWS, Cc, Cc, 0);
    }
    add_ln_kernel<<<MROWS, 256>>>(tgt, tmp, ln2_g, ln2_b, t1);

    // 5) query = t1 + query_pos
    add_kernel<<<(NTOT + 255) / 256, 256>>>(t1, qpos, qk, NTOT);

    // 6) offsets, attention weights, value projection
    {
        dim3 grid(Cc / 128, MROWS / 128);
        gemm_tc_kernel<<<grid, 256, SB>>>(qk, off_w, off_b, off, MROWS, Cc, Cc, 0);
    }
    {
        dim3 grid(1, MROWS / 128);
        gemm_tc_kernel<<<grid, 256, SB>>>(qk, aw_w, aw_b, aw, MROWS, 128, Cc, 0);
    }
    {
        dim3 grid(Cc / 128, VROWS / 128);
        gemm_tc_kernel<<<grid, 256, SB>>>(src, val_w, val_b, val, VROWS, Cc, Cc, 0);
    }

    // 7) deformable sampling
    deform_kernel<<<(MROWS * Hh) / 4, 128>>>(val, off, aw, refp, attn);

    // 8) co proj + residual + LN(ln1) -> t2
    {
        dim3 grid(Cc / 128, MROWS / 128);
        gemm_tc_kernel<<<grid, 256, SB>>>(attn, co_w, co_b, tmp, MROWS, Cc, Cc, 0);
    }
    add_ln_kernel<<<MROWS, 256>>>(t1, tmp, ln1_g, ln1_b, t2);

    // 9) FFN + residual + LN(ln3) -> out
    {
        dim3 grid(DFF / 128, MROWS / 128);
        gemm_tc_kernel<<<grid, 256, SB>>>(t2, f1_w, f1_b, ffn, MROWS, DFF, Cc, 1);
    }
    {
        dim3 grid(Cc / 128, MROWS / 128);
        gemm_tc_kernel<<<grid, 256, SB>>>(ffn, f2_w, f2_b, tmp, MROWS, Cc, DFF, 0);
    }
    add_ln_kernel<<<MROWS, 256>>>(t2, tmp, ln3_g, ln3_b, out);
}

// round 5
// speedup vs baseline: 3.3666x; 1.7377x over previous
#include <cuda_runtime.h>
#include <cuda_bf16.h>
#include <math.h>

#define Bz   4
#define LQ   1024
#define Cc   256
#define Hh   8
#define DH   32
#define DFF  1024
#define LSRC 21760
#define MROWS (Bz*LQ)        // 4096
#define VROWS (Bz*LSRC)      // 87040

// ---------------- scratch (static device globals) ---------------------------
__device__ float g_qk  [MROWS*Cc];
__device__ float g_q   [MROWS*Cc];
__device__ float g_k   [MROWS*Cc];
__device__ float g_v   [MROWS*Cc];
__device__ float g_attn[MROWS*Cc];
__device__ float g_tmp [MROWS*Cc];
__device__ float g_tgt1[MROWS*Cc];
__device__ float g_tgt2[MROWS*Cc];
__device__ float g_off [MROWS*Cc];
__device__ float g_aw  [MROWS*128];
__device__ float g_val [VROWS*Cc];
__device__ float g_ffn [MROWS*DFF];

// ---------------- elementwise add ------------------------------------------
__global__ void add_kernel(const float* __restrict__ a, const float* __restrict__ b,
                           float* __restrict__ y, int n)
{
    int i = blockIdx.x * 256 + threadIdx.x;
    if (i < n) y[i] = a[i] + b[i];
}

// ---------------- tf32 tensor-core GEMM, 3-stage cp.async pipeline ----------
// Y[M,N] = X[M,K] @ W[N,K]^T + bias ; 128x128x32 tile, 256 thr, warp tile 64x32
// Raw fp32 bits fed to tf32 MMA (HW truncates mantissa).
#define GP 36
#define TILE_F (128*GP)
#define STAGE_F (2*TILE_F)
#define GEMM_SMEM_BYTES (3*STAGE_F*4)

template<int K>
__global__ __launch_bounds__(256, 2)
void gemm_tc_kernel(const float* __restrict__ X, const float* __restrict__ W,
                    const float* __restrict__ bias, float* __restrict__ Y,
                    int M, int N, int relu)
{
    extern __shared__ float smem[];

    const int t    = threadIdx.x;
    const int warp = t >> 5;
    const int lane = t & 31;
    const int g    = lane >> 2;
    const int tg   = lane & 3;
    const int warp_m = warp >> 2;
    const int warp_n = warp & 3;
    const int m0 = blockIdx.y * 128;
    const int n0 = blockIdx.x * 128;

    const int lrow = t >> 1;
    const int lcol = (t & 1) * 16;

    float c[4][4][4];
#pragma unroll
    for (int i = 0; i < 4; i++)
#pragma unroll
        for (int j = 0; j < 4; j++)
#pragma unroll
            for (int r = 0; r < 4; r++) c[i][j][r] = 0.f;

    constexpr int NS = K >> 5;

    auto prefetch = [&](int s) {
        const int k0 = s << 5;
        float* xs = smem + (s % 3) * STAGE_F;
        float* ws = xs + TILE_F;
        const float* gx = &X[(size_t)(m0 + lrow) * K + k0 + lcol];
        const float* gw = &W[(size_t)(n0 + lrow) * K + k0 + lcol];
        unsigned sx = (unsigned)__cvta_generic_to_shared(&xs[lrow * GP + lcol]);
        unsigned sw = (unsigned)__cvta_generic_to_shared(&ws[lrow * GP + lcol]);
#pragma unroll
        for (int q = 0; q < 4; q++) {
            asm volatile("cp.async.cg.shared.global [%0], [%1], 16;\n"
                         :: "r"(sx + q * 16), "l"(gx + q * 4));
            asm volatile("cp.async.cg.shared.global [%0], [%1], 16;\n"
                         :: "r"(sw + q * 16), "l"(gw + q * 4));
        }
        asm volatile("cp.async.commit_group;\n");
    };

    prefetch(0);
    prefetch(1);

#pragma unroll
    for (int s = 0; s < NS; s++) {
        if (s < NS - 1) asm volatile("cp.async.wait_group 1;\n");
        else            asm volatile("cp.async.wait_group 0;\n");
        __syncthreads();
        if (s + 2 < NS) prefetch(s + 2);

        const float* xs = smem + (s % 3) * STAGE_F;
        const float* ws = xs + TILE_F;

#pragma unroll
        for (int ks = 0; ks < 4; ks++) {
            const int kk = ks * 8;
            unsigned a[4][4], b[4][2];
#pragma unroll
            for (int mt = 0; mt < 4; mt++) {
                int rb = warp_m * 64 + mt * 16;
                a[mt][0] = __float_as_uint(xs[(rb + g    ) * GP + kk + tg    ]);
                a[mt][1] = __float_as_uint(xs[(rb + g + 8) * GP + kk + tg    ]);
                a[mt][2] = __float_as_uint(xs[(rb + g    ) * GP + kk + tg + 4]);
                a[mt][3] = __float_as_uint(xs[(rb + g + 8) * GP + kk + tg + 4]);
            }
#pragma unroll
            for (int nt = 0; nt < 4; nt++) {
                int nb = warp_n * 32 + nt * 8 + g;
                b[nt][0] = __float_as_uint(ws[nb * GP + kk + tg    ]);
                b[nt][1] = __float_as_uint(ws[nb * GP + kk + tg + 4]);
            }
#pragma unroll
            for (int mt = 0; mt < 4; mt++)
#pragma unroll
                for (int nt = 0; nt < 4; nt++) {
                    asm volatile(
                        "mma.sync.aligned.m16n8k8.row.col.f32.tf32.tf32.f32 "
                        "{%0,%1,%2,%3}, {%4,%5,%6,%7}, {%8,%9}, {%0,%1,%2,%3};"
                        : "+f"(c[mt][nt][0]), "+f"(c[mt][nt][1]),
                          "+f"(c[mt][nt][2]), "+f"(c[mt][nt][3])
                        : "r"(a[mt][0]), "r"(a[mt][1]), "r"(a[mt][2]), "r"(a[mt][3]),
                          "r"(b[nt][0]), "r"(b[nt][1]));
                }
        }
        __syncthreads();
    }

#pragma unroll
    for (int mt = 0; mt < 4; mt++) {
#pragma unroll
        for (int nt = 0; nt < 4; nt++) {
            int col = n0 + warp_n * 32 + nt * 8 + 2 * tg;
            float b0 = bias[col], b1 = bias[col + 1];
            int r0 = m0 + warp_m * 64 + mt * 16 + g;
            float v0 = c[mt][nt][0] + b0;
            float v1 = c[mt][nt][1] + b1;
            float v2 = c[mt][nt][2] + b0;
            float v3 = c[mt][nt][3] + b1;
            if (relu) {
                v0 = fmaxf(v0, 0.f); v1 = fmaxf(v1, 0.f);
                v2 = fmaxf(v2, 0.f); v3 = fmaxf(v3, 0.f);
            }
            Y[(size_t)r0 * N + col]           = v0;
            Y[(size_t)r0 * N + col + 1]       = v1;
            Y[(size_t)(r0 + 8) * N + col]     = v2;
            Y[(size_t)(r0 + 8) * N + col + 1] = v3;
        }
    }
}

// ---------------- residual + LayerNorm (row = 256) --------------------------
__global__ void add_ln_kernel(const float* __restrict__ A, const float* __restrict__ Bv,
                              const float* __restrict__ g, const float* __restrict__ be,
                              float* __restrict__ Y)
{
    int row = blockIdx.x, t = threadIdx.x;
    float x = A[(size_t)row * Cc + t] + Bv[(size_t)row * Cc + t];
    float s = x, s2 = x * x;
#pragma unroll
    for (int o = 16; o > 0; o >>= 1) {
        s  += __shfl_xor_sync(0xffffffffu, s, o);
        s2 += __shfl_xor_sync(0xffffffffu, s2, o);
    }
    __shared__ float ss[8], ss2[8];
    int w = t >> 5;
    if ((t & 31) == 0) { ss[w] = s; ss2[w] = s2; }
    __syncthreads();
    s = 0.f; s2 = 0.f;
#pragma unroll
    for (int i = 0; i < 8; i++) { s += ss[i]; s2 += ss2[i]; }
    float mean = s * (1.f / Cc);
    float var  = s2 * (1.f / Cc) - mean * mean;
    float inv  = rsqrtf(var + 1e-5f);
    Y[(size_t)row * Cc + t] = (x - mean) * inv * g[t] + be[t];
}

// ---------------- MHA attention v2: 64 queries / block ----------------------
// grid (LQ/64, B*H), 256 thr. warp owns 8 queries; lane: q = 8*warp + lane/4,
// quad = lane&3 owns 16-key slice per chunk and 8-channel output slice.
// K/V chunks in smem with per-16-row XOR granule swizzle (conflict-free).
__global__ __launch_bounds__(256)
void attn_kernel(const float* __restrict__ Q, const float* __restrict__ K,
                 const float* __restrict__ V, float* __restrict__ O)
{
    __shared__ float Ks[64 * 32];
    __shared__ float Vs[64 * 32];

    const int t = threadIdx.x;
    const int warp = t >> 5, lane = t & 31;
    const int quad = lane & 3, qi = lane >> 2;
    const int bh = blockIdx.y;
    const int b = bh >> 3, h = bh & 7;
    const int q = blockIdx.x * 64 + warp * 8 + qi;
    const size_t qrow = (size_t)(b * LQ + q) * Cc + h * DH;

    float qreg[32];
#pragma unroll
    for (int d4 = 0; d4 < 8; d4++) {
        float4 v4 = *(const float4*)&Q[qrow + d4 * 4];
        qreg[d4*4+0] = v4.x * 0.17677669529663687f;
        qreg[d4*4+1] = v4.y * 0.17677669529663687f;
        qreg[d4*4+2] = v4.z * 0.17677669529663687f;
        qreg[d4*4+3] = v4.w * 0.17677669529663687f;
    }

    float m = -1e30f, l = 0.f;
    float acc[8];
#pragma unroll
    for (int i = 0; i < 8; i++) acc[i] = 0.f;

    for (int c0 = 0; c0 < LQ; c0 += 64) {
        __syncthreads();
        // fill K and V chunks (each thread: 2 granules of K + 2 of V)
#pragma unroll
        for (int j = 0; j < 2; j++) {
            int gl = t * 2 + j;
            int row = gl >> 3, g = gl & 7;
            int gsw = g ^ ((row >> 4) & 3);
            size_t srcoff = (size_t)(b * LQ + c0 + row) * Cc + h * DH + g * 4;
            *(float4*)&Ks[row * 32 + gsw * 4] = *(const float4*)&K[srcoff];
            *(float4*)&Vs[row * 32 + gsw * 4] = *(const float4*)&V[srcoff];
        }
        __syncthreads();

        // scores for this quad's 16 keys
        float p[16];
        float mx = -1e30f;
#pragma unroll
        for (int i = 0; i < 16; i++) {
            const int k = quad * 16 + i;       // (k>>4)&3 == quad
            const float* kr = Ks + k * 32;
            float s = 0.f;
#pragma unroll
            for (int g = 0; g < 8; g++) {
                float4 kv = *(const float4*)(kr + ((g ^ quad) << 2));
                s += qreg[g*4+0] * kv.x + qreg[g*4+1] * kv.y
                   + qreg[g*4+2] * kv.z + qreg[g*4+3] * kv.w;
            }
            p[i] = s;
            mx = fmaxf(mx, s);
        }
        // quad-uniform chunk max
        mx = fmaxf(mx, __shfl_xor_sync(0xffffffffu, mx, 1));
        mx = fmaxf(mx, __shfl_xor_sync(0xffffffffu, mx, 2));
        float mnew = fmaxf(m, mx);
        float corr = __expf(m - mnew);
        l *= corr;
#pragma unroll
        for (int i = 0; i < 8; i++) acc[i] *= corr;
#pragma unroll
        for (int i = 0; i < 16; i++) { p[i] = __expf(p[i] - mnew); l += p[i]; }
        m = mnew;

        // PV: broadcast p within quad, accumulate own 8-channel slice
#pragma unroll
        for (int kk = 0; kk < 64; kk++) {
            float pv = __shfl_sync(0xffffffffu, p[kk & 15], kk >> 4, 4);
            const float* vr = Vs + kk * 32;
            const int sw = (kk >> 4) & 3;
            float4 v0 = *(const float4*)(vr + (((quad * 2    ) ^ sw) << 2));
            float4 v1 = *(const float4*)(vr + (((quad * 2 + 1) ^ sw) << 2));
            acc[0] += pv * v0.x; acc[1] += pv * v0.y;
            acc[2] += pv * v0.z; acc[3] += pv * v0.w;
            acc[4] += pv * v1.x; acc[5] += pv * v1.y;
            acc[6] += pv * v1.z; acc[7] += pv * v1.w;
        }
    }

    // quad-reduce l (m already quad-uniform)
    l += __shfl_xor_sync(0xffffffffu, l, 1);
    l += __shfl_xor_sync(0xffffffffu, l, 2);
    float inv = 1.f / l;

    float4 o0 = make_float4(acc[0]*inv, acc[1]*inv, acc[2]*inv, acc[3]*inv);
    float4 o1 = make_float4(acc[4]*inv, acc[5]*inv, acc[6]*inv, acc[7]*inv);
    *(float4*)&O[qrow + quad * 8    ] = o0;
    *(float4*)&O[qrow + quad * 8 + 4] = o1;
}

// ---------------- deformable sampling (warp per (b,q,h), lane = channel) ----
__global__ void deform_kernel(const float* __restrict__ val, const float* __restrict__ offs,
                              const float* __restrict__ awl, const float* __restrict__ ref,
                              float* __restrict__ out)
{
    const int gid  = blockIdx.x * 4 + (threadIdx.x >> 5);
    const int lane = threadIdx.x & 31;
    const int h   = gid & 7;
    const int row = gid >> 3;
    const int b   = row >> 10;

    float a[16];
    float mx = -1e30f;
#pragma unroll
    for (int i = 0; i < 16; i++) {
        a[i] = awl[(size_t)row * 128 + h * 16 + i];
        mx = fmaxf(mx, a[i]);
    }
    float ssum = 0.f;
#pragma unroll
    for (int i = 0; i < 16; i++) { a[i] = __expf(a[i] - mx); ssum += a[i]; }
    float invs = 1.f / ssum;

    const int starts[4] = {0, 16384, 20480, 21504};
    float acc = 0.f;
#pragma unroll
    for (int lvl = 0; lvl < 4; lvl++) {
        const int Wl = 128 >> lvl;
        const int Hl = 128 >> lvl;
        const int start = starts[lvl];
        float rx = ref[((size_t)row * 4 + lvl) * 2 + 0];
        float ry = ref[((size_t)row * 4 + lvl) * 2 + 1];
#pragma unroll
        for (int p = 0; p < 4; p++) {
            size_t obase = (size_t)row * 256 + (((h * 4 + lvl) * 4 + p) * 2);
            float ox = offs[obase + 0];
            float oy = offs[obase + 1];
            float x = rx * (float)Wl + ox - 0.5f;
            float y = ry * (float)Hl + oy - 0.5f;
            float xf = floorf(x), yf = floorf(y);
            int x0 = (int)xf, y0 = (int)yf;
            float wx1 = x - xf, wx0 = 1.f - wx1;
            float wy1 = y - yf, wy0 = 1.f - wy1;
            float aw = a[lvl * 4 + p] * invs;

            float w00 = wx0 * wy0 * aw, w10 = wx1 * wy0 * aw;
            float w01 = wx0 * wy1 * aw, w11 = wx1 * wy1 * aw;
#pragma unroll
            for (int cidx = 0; cidx < 4; cidx++) {
                int ix = x0 + (cidx & 1);
                int iy = y0 + (cidx >> 1);
                float w = (cidx == 0) ? w00 : (cidx == 1) ? w10 : (cidx == 2) ? w01 : w11;
                if (ix >= 0 && ix < Wl && iy >= 0 && iy < Hl) {
                    size_t idx = (size_t)(b * LSRC + start + iy * Wl + ix) * Cc + h * DH + lane;
                    acc += w * val[idx];
                }
            }
        }
    }
    out[(size_t)row * Cc + h * DH + lane] = acc;
}

// ---------------- launcher ---------------------------------------------------
extern "C" void kernel_launch(void* const* d_in, const int* in_sizes, int n_in,
                              void* d_out, int out_size)
{
    const float* tgt   = (const float*)d_in[0];
    const float* qpos  = (const float*)d_in[1];
    const float* refp  = (const float*)d_in[2];
    const float* src   = (const float*)d_in[3];
    const float* in_w  = (const float*)d_in[4];
    const float* in_b  = (const float*)d_in[5];
    const float* sa_w  = (const float*)d_in[6];
    const float* sa_b  = (const float*)d_in[7];
    const float* off_w = (const float*)d_in[8];
    const float* off_b = (const float*)d_in[9];
    const float* aw_w  = (const float*)d_in[10];
    const float* aw_b  = (const float*)d_in[11];
    const float* val_w = (const float*)d_in[12];
    const float* val_b = (const float*)d_in[13];
    const float* co_w  = (const float*)d_in[14];
    const float* co_b  = (const float*)d_in[15];
    const float* ln1_g = (const float*)d_in[16];
    const float* ln1_b = (const float*)d_in[17];
    const float* ln2_g = (const float*)d_in[18];
    const float* ln2_b = (const float*)d_in[19];
    const float* ln3_g = (const float*)d_in[20];
    const float* ln3_b = (const float*)d_in[21];
    const float* f1_w  = (const float*)d_in[22];
    const float* f1_b  = (const float*)d_in[23];
    const float* f2_w  = (const float*)d_in[24];
    const float* f2_b  = (const float*)d_in[25];
    float* out = (float*)d_out;

    float *qk, *q, *k, *v, *attn, *tmp, *t1, *t2, *off, *aw, *val, *ffn;
    cudaGetSymbolAddress((void**)&qk,   g_qk);
    cudaGetSymbolAddress((void**)&q,    g_q);
    cudaGetSymbolAddress((void**)&k,    g_k);
    cudaGetSymbolAddress((void**)&v,    g_v);
    cudaGetSymbolAddress((void**)&attn, g_attn);
    cudaGetSymbolAddress((void**)&tmp,  g_tmp);
    cudaGetSymbolAddress((void**)&t1,   g_tgt1);
    cudaGetSymbolAddress((void**)&t2,   g_tgt2);
    cudaGetSymbolAddress((void**)&off,  g_off);
    cudaGetSymbolAddress((void**)&aw,   g_aw);
    cudaGetSymbolAddress((void**)&val,  g_val);
    cudaGetSymbolAddress((void**)&ffn,  g_ffn);

    cudaFuncSetAttribute(gemm_tc_kernel<256>,
                         cudaFuncAttributeMaxDynamicSharedMemorySize, GEMM_SMEM_BYTES);
    cudaFuncSetAttribute(gemm_tc_kernel<1024>,
                         cudaFuncAttributeMaxDynamicSharedMemorySize, GEMM_SMEM_BYTES);

    const int NTOT = MROWS * Cc;
    const int SB = GEMM_SMEM_BYTES;

    // 1) qk = tgt + query_pos
    add_kernel<<<(NTOT + 255) / 256, 256>>>(tgt, qpos, qk, NTOT);

    // 2) Q/K/V projections
    {
        dim3 grid(Cc / 128, MROWS / 128);
        gemm_tc_kernel<256><<<grid, 256, SB>>>(qk,  in_w,          in_b,       q, MROWS, Cc, 0);
        gemm_tc_kernel<256><<<grid, 256, SB>>>(qk,  in_w + 256*Cc, in_b + 256, k, MROWS, Cc, 0);
        gemm_tc_kernel<256><<<grid, 256, SB>>>(tgt, in_w + 512*Cc, in_b + 512, v, MROWS, Cc, 0);
    }

    // 3) attention
    {
        dim3 grid(LQ / 64, Bz * Hh);
        attn_kernel<<<grid, 256>>>(q, k, v, attn);
    }

    // 4) self-attn out proj + residual + LN(ln2) -> t1
    {
        dim3 grid(Cc / 128, MROWS / 128);
        gemm_tc_kernel<256><<<grid, 256, SB>>>(attn, sa_w, sa_b, tmp, MROWS, Cc, 0);
    }
    add_ln_kernel<<<MROWS, 256>>>(tgt, tmp, ln2_g, ln2_b, t1);

    // 5) query = t1 + query_pos
    add_kernel<<<(NTOT + 255) / 256, 256>>>(t1, qpos, qk, NTOT);

    // 6) offsets, attention weights, value projection
    {
        dim3 grid(Cc / 128, MROWS / 128);
        gemm_tc_kernel<256><<<grid, 256, SB>>>(qk, off_w, off_b, off, MROWS, Cc, 0);
    }
    {
        dim3 grid(1, MROWS / 128);
        gemm_tc_kernel<256><<<grid, 256, SB>>>(qk, aw_w, aw_b, aw, MROWS, 128, 0);
    }
    {
        dim3 grid(Cc / 128, VROWS / 128);
        gemm_tc_kernel<256><<<grid, 256, SB>>>(src, val_w, val_b, val, VROWS, Cc, 0);
    }

    // 7) deformable sampling
    deform_kernel<<<(MROWS * Hh) / 4, 128>>>(val, off, aw, refp, attn);

    // 8) co proj + residual + LN(ln1) -> t2
    {
        dim3 grid(Cc / 128, MROWS / 128);
        gemm_tc_kernel<256><<<grid, 256, SB>>>(attn, co_w, co_b, tmp, MROWS, Cc, 0);
    }
    add_ln_kernel<<<MROWS, 256>>>(t1, tmp, ln1_g, ln1_b, t2);

    // 9) FFN + residual + LN(ln3) -> out
    {
        dim3 grid(DFF / 128, MROWS / 128);
        gemm_tc_kernel<256><<<grid, 256, SB>>>(t2, f1_w, f1_b, ffn, MROWS, DFF, 1);
    }
    {
        dim3 grid(Cc / 128, MROWS / 128);
        gemm_tc_kernel<1024><<<grid, 256, SB>>>(ffn, f2_w, f2_b, tmp, MROWS, Cc, 0);
    }
    add_ln_kernel<<<MROWS, 256>>>(t2, tmp, ln3_g, ln3_b, out);
}

// round 6
// speedup vs baseline: 3.5453x; 1.0531x over previous
#include <cuda_runtime.h>
#include <cuda_bf16.h>
#include <math.h>

#define Bz   4
#define LQ   1024
#define Cc   256
#define Hh   8
#define DH   32
#define DFF  1024
#define LSRC 21760
#define MROWS (Bz*LQ)        // 4096
#define VROWS (Bz*LSRC)      // 87040

// ---------------- scratch (static device globals) ---------------------------
__device__ float g_qk  [MROWS*Cc];
__device__ float g_qkv [3*MROWS*Cc];
__device__ float g_attn[MROWS*Cc];
__device__ float g_tmp [MROWS*Cc];
__device__ float g_tgt1[MROWS*Cc];
__device__ float g_tgt2[MROWS*Cc];
__device__ float g_off [MROWS*Cc];
__device__ float g_aw  [MROWS*128];
__device__ float g_val [VROWS*Cc];
__device__ float g_ffn [MROWS*DFF];

// ---------------- elementwise add ------------------------------------------
__global__ void add_kernel(const float* __restrict__ a, const float* __restrict__ b,
                           float* __restrict__ y, int n)
{
    int i = blockIdx.x * 256 + threadIdx.x;
    if (i < n) y[i] = a[i] + b[i];
}

// ---------------- tf32 tensor-core GEMM, 2-stage, 1 barrier per K-step ------
// Y[M,N] = X[M,K] @ W[N,K]^T + bias. Block tile 128 x BN, 256 thr (8 warps,
// 2x4). Warp tile 64 x BN/4. Raw fp32 bits as tf32 operands.
// blockIdx.z batches independent GEMMs sharing layout (QKV): z picks weight
// block z*256 rows, bias z*256, output slice z*M*N, and X2 for z==2.
#define GP 36
template<int K, int BN>
__global__ __launch_bounds__(256, 2)
void gemm_tc(const float* __restrict__ X, const float* __restrict__ Xalt,
             const float* __restrict__ W, const float* __restrict__ bias,
             float* __restrict__ Y, int M, int N, int relu)
{
    extern __shared__ float smem[];
    constexpr int NT = BN / 32;            // nt count (warp tile N / 8)
    constexpr int XTILE_F = 128 * GP;
    constexpr int WTILE_F = BN * GP;
    constexpr int STAGE = XTILE_F + WTILE_F;
    constexpr int NS = K >> 5;
    constexpr int TPR = 256 / BN;          // threads per W row (2 or 4)
    constexpr int WG  = (32 / TPR) / 4;    // 16B granules per thread for W

    const int z = blockIdx.z;
    if (z) {
        W    += (size_t)z * 256 * K;
        bias += z * 256;
        Y    += (size_t)z * M * N;
        if (z == 2) X = Xalt;
    }

    const int t    = threadIdx.x;
    const int warp = t >> 5;
    const int lane = t & 31;
    const int g    = lane >> 2;
    const int tg   = lane & 3;
    const int warp_m = warp >> 2;          // 0..1
    const int warp_n = warp & 3;           // 0..3
    const int m0 = blockIdx.y * 128;
    const int n0 = blockIdx.x * BN;

    const int xrow = t >> 1;               // 0..127
    const int xcol = (t & 1) * 16;
    const int wrow = t / TPR;              // 0..BN-1
    const int wcol = (t % TPR) * (32 / TPR);

    float c[4][NT][4];
#pragma unroll
    for (int i = 0; i < 4; i++)
#pragma unroll
        for (int j = 0; j < NT; j++)
#pragma unroll
            for (int r = 0; r < 4; r++) c[i][j][r] = 0.f;

    auto prefetch = [&](int s) {
        const int k0 = s << 5;
        float* xs = smem + (s & 1) * STAGE;
        float* ws = xs + XTILE_F;
        const float* gx = &X[(size_t)(m0 + xrow) * K + k0 + xcol];
        unsigned sx = (unsigned)__cvta_generic_to_shared(&xs[xrow * GP + xcol]);
#pragma unroll
        for (int q = 0; q < 4; q++)
            asm volatile("cp.async.cg.shared.global [%0], [%1], 16;\n"
                         :: "r"(sx + q * 16), "l"(gx + q * 4));
        const float* gw = &W[(size_t)(n0 + wrow) * K + k0 + wcol];
        unsigned sw = (unsigned)__cvta_generic_to_shared(&ws[wrow * GP + wcol]);
#pragma unroll
        for (int q = 0; q < WG; q++)
            asm volatile("cp.async.cg.shared.global [%0], [%1], 16;\n"
                         :: "r"(sw + q * 16), "l"(gw + q * 4));
        asm volatile("cp.async.commit_group;\n");
    };

    prefetch(0);

#pragma unroll
    for (int s = 0; s < NS; s++) {
        asm volatile("cp.async.wait_group 0;\n");
        __syncthreads();                    // all warps done with buf (s+1)&1
        if (s + 1 < NS) prefetch(s + 1);    // overlaps with compute below

        const float* xs = smem + (s & 1) * STAGE;
        const float* ws = xs + XTILE_F;

#pragma unroll
        for (int ks = 0; ks < 4; ks++) {
            const int kk = ks * 8;
            unsigned a[4][4], b[NT][2];
#pragma unroll
            for (int mt = 0; mt < 4; mt++) {
                int rb = warp_m * 64 + mt * 16;
                a[mt][0] = __float_as_uint(xs[(rb + g    ) * GP + kk + tg    ]);
                a[mt][1] = __float_as_uint(xs[(rb + g + 8) * GP + kk + tg    ]);
                a[mt][2] = __float_as_uint(xs[(rb + g    ) * GP + kk + tg + 4]);
                a[mt][3] = __float_as_uint(xs[(rb + g + 8) * GP + kk + tg + 4]);
            }
#pragma unroll
            for (int nt = 0; nt < NT; nt++) {
                int nb = warp_n * (BN / 4) + nt * 8 + g;
                b[nt][0] = __float_as_uint(ws[nb * GP + kk + tg    ]);
                b[nt][1] = __float_as_uint(ws[nb * GP + kk + tg + 4]);
            }
#pragma unroll
            for (int mt = 0; mt < 4; mt++)
#pragma unroll
                for (int nt = 0; nt < NT; nt++) {
                    asm volatile(
                        "mma.sync.aligned.m16n8k8.row.col.f32.tf32.tf32.f32 "
                        "{%0,%1,%2,%3}, {%4,%5,%6,%7}, {%8,%9}, {%0,%1,%2,%3};"
                        : "+f"(c[mt][nt][0]), "+f"(c[mt][nt][1]),
                          "+f"(c[mt][nt][2]), "+f"(c[mt][nt][3])
                        : "r"(a[mt][0]), "r"(a[mt][1]), "r"(a[mt][2]), "r"(a[mt][3]),
                          "r"(b[nt][0]), "r"(b[nt][1]));
                }
        }
    }

#pragma unroll
    for (int mt = 0; mt < 4; mt++) {
#pragma unroll
        for (int nt = 0; nt < NT; nt++) {
            int col = n0 + warp_n * (BN / 4) + nt * 8 + 2 * tg;
            float b0 = bias[col], b1 = bias[col + 1];
            int r0 = m0 + warp_m * 64 + mt * 16 + g;
            float v0 = c[mt][nt][0] + b0;
            float v1 = c[mt][nt][1] + b1;
            float v2 = c[mt][nt][2] + b0;
            float v3 = c[mt][nt][3] + b1;
            if (relu) {
                v0 = fmaxf(v0, 0.f); v1 = fmaxf(v1, 0.f);
                v2 = fmaxf(v2, 0.f); v3 = fmaxf(v3, 0.f);
            }
            Y[(size_t)r0 * N + col]           = v0;
            Y[(size_t)r0 * N + col + 1]       = v1;
            Y[(size_t)(r0 + 8) * N + col]     = v2;
            Y[(size_t)(r0 + 8) * N + col + 1] = v3;
        }
    }
}

#define SMEMB(BN) (2 * (128 + (BN)) * GP * 4)

// ---------------- residual + LayerNorm (row = 256) --------------------------
__global__ void add_ln_kernel(const float* __restrict__ A, const float* __restrict__ Bv,
                              const float* __restrict__ g, const float* __restrict__ be,
                              float* __restrict__ Y)
{
    int row = blockIdx.x, t = threadIdx.x;
    float x = A[(size_t)row * Cc + t] + Bv[(size_t)row * Cc + t];
    float s = x, s2 = x * x;
#pragma unroll
    for (int o = 16; o > 0; o >>= 1) {
        s  += __shfl_xor_sync(0xffffffffu, s, o);
        s2 += __shfl_xor_sync(0xffffffffu, s2, o);
    }
    __shared__ float ss[8], ss2[8];
    int w = t >> 5;
    if ((t & 31) == 0) { ss[w] = s; ss2[w] = s2; }
    __syncthreads();
    s = 0.f; s2 = 0.f;
#pragma unroll
    for (int i = 0; i < 8; i++) { s += ss[i]; s2 += ss2[i]; }
    float mean = s * (1.f / Cc);
    float var  = s2 * (1.f / Cc) - mean * mean;
    float inv  = rsqrtf(var + 1e-5f);
    Y[(size_t)row * Cc + t] = (x - mean) * inv * g[t] + be[t];
}

// ---------------- MHA attention: 64 queries / block --------------------------
__global__ __launch_bounds__(256)
void attn_kernel(const float* __restrict__ Q, const float* __restrict__ K,
                 const float* __restrict__ V, float* __restrict__ O)
{
    __shared__ float Ks[64 * 32];
    __shared__ float Vs[64 * 32];

    const int t = threadIdx.x;
    const int warp = t >> 5, lane = t & 31;
    const int quad = lane & 3, qi = lane >> 2;
    const int bh = blockIdx.y;
    const int b = bh >> 3, h = bh & 7;
    const int q = blockIdx.x * 64 + warp * 8 + qi;
    const size_t qrow = (size_t)(b * LQ + q) * Cc + h * DH;

    float qreg[32];
#pragma unroll
    for (int d4 = 0; d4 < 8; d4++) {
        float4 v4 = *(const float4*)&Q[qrow + d4 * 4];
        qreg[d4*4+0] = v4.x * 0.17677669529663687f;
        qreg[d4*4+1] = v4.y * 0.17677669529663687f;
        qreg[d4*4+2] = v4.z * 0.17677669529663687f;
        qreg[d4*4+3] = v4.w * 0.17677669529663687f;
    }

    float m = -1e30f, l = 0.f;
    float acc[8];
#pragma unroll
    for (int i = 0; i < 8; i++) acc[i] = 0.f;

    for (int c0 = 0; c0 < LQ; c0 += 64) {
        __syncthreads();
#pragma unroll
        for (int j = 0; j < 2; j++) {
            int gl = t * 2 + j;
            int row = gl >> 3, g = gl & 7;
            int gsw = g ^ ((row >> 4) & 3);
            size_t srcoff = (size_t)(b * LQ + c0 + row) * Cc + h * DH + g * 4;
            *(float4*)&Ks[row * 32 + gsw * 4] = *(const float4*)&K[srcoff];
            *(float4*)&Vs[row * 32 + gsw * 4] = *(const float4*)&V[srcoff];
        }
        __syncthreads();

        float p[16];
        float mx = -1e30f;
#pragma unroll
        for (int i = 0; i < 16; i++) {
            const int k = quad * 16 + i;
            const float* kr = Ks + k * 32;
            float s = 0.f;
#pragma unroll
            for (int g = 0; g < 8; g++) {
                float4 kv = *(const float4*)(kr + ((g ^ quad) << 2));
                s += qreg[g*4+0] * kv.x + qreg[g*4+1] * kv.y
                   + qreg[g*4+2] * kv.z + qreg[g*4+3] * kv.w;
            }
            p[i] = s;
            mx = fmaxf(mx, s);
        }
        mx = fmaxf(mx, __shfl_xor_sync(0xffffffffu, mx, 1));
        mx = fmaxf(mx, __shfl_xor_sync(0xffffffffu, mx, 2));
        float mnew = fmaxf(m, mx);
        float corr = __expf(m - mnew);
        l *= corr;
#pragma unroll
        for (int i = 0; i < 8; i++) acc[i] *= corr;
#pragma unroll
        for (int i = 0; i < 16; i++) { p[i] = __expf(p[i] - mnew); l += p[i]; }
        m = mnew;

#pragma unroll
        for (int kk = 0; kk < 64; kk++) {
            float pv = __shfl_sync(0xffffffffu, p[kk & 15], kk >> 4, 4);
            const float* vr = Vs + kk * 32;
            const int sw = (kk >> 4) & 3;
            float4 v0 = *(const float4*)(vr + (((quad * 2    ) ^ sw) << 2));
            float4 v1 = *(const float4*)(vr + (((quad * 2 + 1) ^ sw) << 2));
            acc[0] += pv * v0.x; acc[1] += pv * v0.y;
            acc[2] += pv * v0.z; acc[3] += pv * v0.w;
            acc[4] += pv * v1.x; acc[5] += pv * v1.y;
            acc[6] += pv * v1.z; acc[7] += pv * v1.w;
        }
    }

    l += __shfl_xor_sync(0xffffffffu, l, 1);
    l += __shfl_xor_sync(0xffffffffu, l, 2);
    float inv = 1.f / l;

    float4 o0 = make_float4(acc[0]*inv, acc[1]*inv, acc[2]*inv, acc[3]*inv);
    float4 o1 = make_float4(acc[4]*inv, acc[5]*inv, acc[6]*inv, acc[7]*inv);
    *(float4*)&O[qrow + quad * 8    ] = o0;
    *(float4*)&O[qrow + quad * 8 + 4] = o1;
}

// ---------------- deformable sampling (warp per (b,q,h), lane = channel) ----
__global__ void deform_kernel(const float* __restrict__ val, const float* __restrict__ offs,
                              const float* __restrict__ awl, const float* __restrict__ ref,
                              float* __restrict__ out)
{
    const int gid  = blockIdx.x * 4 + (threadIdx.x >> 5);
    const int lane = threadIdx.x & 31;
    const int h   = gid & 7;
    const int row = gid >> 3;
    const int b   = row >> 10;

    float a[16];
    float mx = -1e30f;
#pragma unroll
    for (int i = 0; i < 16; i++) {
        a[i] = awl[(size_t)row * 128 + h * 16 + i];
        mx = fmaxf(mx, a[i]);
    }
    float ssum = 0.f;
#pragma unroll
    for (int i = 0; i < 16; i++) { a[i] = __expf(a[i] - mx); ssum += a[i]; }
    float invs = 1.f / ssum;

    const int starts[4] = {0, 16384, 20480, 21504};
    float acc = 0.f;
#pragma unroll
    for (int lvl = 0; lvl < 4; lvl++) {
        const int Wl = 128 >> lvl;
        const int Hl = 128 >> lvl;
        const int start = starts[lvl];
        float rx = ref[((size_t)row * 4 + lvl) * 2 + 0];
        float ry = ref[((size_t)row * 4 + lvl) * 2 + 1];
#pragma unroll
        for (int p = 0; p < 4; p++) {
            size_t obase = (size_t)row * 256 + (((h * 4 + lvl) * 4 + p) * 2);
            float ox = offs[obase + 0];
            float oy = offs[obase + 1];
            float x = rx * (float)Wl + ox - 0.5f;
            float y = ry * (float)Hl + oy - 0.5f;
            float xf = floorf(x), yf = floorf(y);
            int x0 = (int)xf, y0 = (int)yf;
            float wx1 = x - xf, wx0 = 1.f - wx1;
            float wy1 = y - yf, wy0 = 1.f - wy1;
            float aw = a[lvl * 4 + p] * invs;

            float w00 = wx0 * wy0 * aw, w10 = wx1 * wy0 * aw;
            float w01 = wx0 * wy1 * aw, w11 = wx1 * wy1 * aw;
#pragma unroll
            for (int cidx = 0; cidx < 4; cidx++) {
                int ix = x0 + (cidx & 1);
                int iy = y0 + (cidx >> 1);
                float w = (cidx == 0) ? w00 : (cidx == 1) ? w10 : (cidx == 2) ? w01 : w11;
                if (ix >= 0 && ix < Wl && iy >= 0 && iy < Hl) {
                    size_t idx = (size_t)(b * LSRC + start + iy * Wl + ix) * Cc + h * DH + lane;
                    acc += w * val[idx];
                }
            }
        }
    }
    out[(size_t)row * Cc + h * DH + lane] = acc;
}

// ---------------- launcher ---------------------------------------------------
extern "C" void kernel_launch(void* const* d_in, const int* in_sizes, int n_in,
                              void* d_out, int out_size)
{
    const float* tgt   = (const float*)d_in[0];
    const float* qpos  = (const float*)d_in[1];
    const float* refp  = (const float*)d_in[2];
    const float* src   = (const float*)d_in[3];
    const float* in_w  = (const float*)d_in[4];
    const float* in_b  = (const float*)d_in[5];
    const float* sa_w  = (const float*)d_in[6];
    const float* sa_b  = (const float*)d_in[7];
    const float* off_w = (const float*)d_in[8];
    const float* off_b = (const float*)d_in[9];
    const float* aw_w  = (const float*)d_in[10];
    const float* aw_b  = (const float*)d_in[11];
    const float* val_w = (const float*)d_in[12];
    const float* val_b = (const float*)d_in[13];
    const float* co_w  = (const float*)d_in[14];
    const float* co_b  = (const float*)d_in[15];
    const float* ln1_g = (const float*)d_in[16];
    const float* ln1_b = (const float*)d_in[17];
    const float* ln2_g = (const float*)d_in[18];
    const float* ln2_b = (const float*)d_in[19];
    const float* ln3_g = (const float*)d_in[20];
    const float* ln3_b = (const float*)d_in[21];
    const float* f1_w  = (const float*)d_in[22];
    const float* f1_b  = (const float*)d_in[23];
    const float* f2_w  = (const float*)d_in[24];
    const float* f2_b  = (const float*)d_in[25];
    float* out = (float*)d_out;

    float *qk, *qkv, *attn, *tmp, *t1, *t2, *off, *aw, *val, *ffn;
    cudaGetSymbolAddress((void**)&qk,   g_qk);
    cudaGetSymbolAddress((void**)&qkv,  g_qkv);
    cudaGetSymbolAddress((void**)&attn, g_attn);
    cudaGetSymbolAddress((void**)&tmp,  g_tmp);
    cudaGetSymbolAddress((void**)&t1,   g_tgt1);
    cudaGetSymbolAddress((void**)&t2,   g_tgt2);
    cudaGetSymbolAddress((void**)&off,  g_off);
    cudaGetSymbolAddress((void**)&aw,   g_aw);
    cudaGetSymbolAddress((void**)&val,  g_val);
    cudaGetSymbolAddress((void**)&ffn,  g_ffn);

    cudaFuncSetAttribute(gemm_tc<256,64>,
                         cudaFuncAttributeMaxDynamicSharedMemorySize, SMEMB(64));
    cudaFuncSetAttribute(gemm_tc<256,128>,
                         cudaFuncAttributeMaxDynamicSharedMemorySize, SMEMB(128));
    cudaFuncSetAttribute(gemm_tc<1024,64>,
                         cudaFuncAttributeMaxDynamicSharedMemorySize, SMEMB(64));

    const int NTOT = MROWS * Cc;

    // 1) qk = tgt + query_pos
    add_kernel<<<(NTOT + 255) / 256, 256>>>(tgt, qpos, qk, NTOT);

    // 2) Q/K/V projections — batched over grid.z (z==2 uses tgt as input)
    gemm_tc<256,64><<<dim3(4, 32, 3), 256, SMEMB(64)>>>(
        qk, tgt, in_w, in_b, qkv, MROWS, Cc, 0);

    // 3) attention
    attn_kernel<<<dim3(LQ / 64, Bz * Hh), 256>>>(
        qkv, qkv + MROWS * Cc, qkv + 2 * MROWS * Cc, attn);

    // 4) self-attn out proj + residual + LN(ln2) -> t1
    gemm_tc<256,64><<<dim3(4, 32), 256, SMEMB(64)>>>(
        attn, nullptr, sa_w, sa_b, tmp, MROWS, Cc, 0);
    add_ln_kernel<<<MROWS, 256>>>(tgt, tmp, ln2_g, ln2_b, t1);

    // 5) query = t1 + query_pos
    add_kernel<<<(NTOT + 255) / 256, 256>>>(t1, qpos, qk, NTOT);

    // 6) offsets, attention weights, value projection
    gemm_tc<256,64><<<dim3(4, 32), 256, SMEMB(64)>>>(
        qk, nullptr, off_w, off_b, off, MROWS, Cc, 0);
    gemm_tc<256,64><<<dim3(2, 32), 256, SMEMB(64)>>>(
        qk, nullptr, aw_w, aw_b, aw, MROWS, 128, 0);
    gemm_tc<256,128><<<dim3(2, VROWS / 128), 256, SMEMB(128)>>>(
        src, nullptr, val_w, val_b, val, VROWS, Cc, 0);

    // 7) deformable sampling
    deform_kernel<<<(MROWS * Hh) / 4, 128>>>(val, off, aw, refp, attn);

    // 8) co proj + residual + LN(ln1) -> t2
    gemm_tc<256,64><<<dim3(4, 32), 256, SMEMB(64)>>>(
        attn, nullptr, co_w, co_b, tmp, MROWS, Cc, 0);
    add_ln_kernel<<<MROWS, 256>>>(t1, tmp, ln1_g, ln1_b, t2);

    // 9) FFN + residual + LN(ln3) -> out
    gemm_tc<256,64><<<dim3(16, 32), 256, SMEMB(64)>>>(
        t2, nullptr, f1_w, f1_b, ffn, MROWS, DFF, 1);
    gemm_tc<1024,64><<<dim3(4, 32), 256, SMEMB(64)>>>(
        ffn, nullptr, f2_w, f2_b, tmp, MROWS, Cc, 0);
    add_ln_kernel<<<MROWS, 256>>>(t2, tmp, ln3_g, ln3_b, out);
}

// round 7
// speedup vs baseline: 3.6012x; 1.0158x over previous
#include <cuda_runtime.h>
#include <cuda_bf16.h>
#include <math.h>

#define Bz   4
#define LQ   1024
#define Cc   256
#define Hh   8
#define DH   32
#define DFF  1024
#define LSRC 21760
#define MROWS (Bz*LQ)        // 4096
#define VROWS (Bz*LSRC)      // 87040

// ---------------- scratch (static device globals) ---------------------------
__device__ float g_qk  [MROWS*Cc];
__device__ float g_qk2 [MROWS*Cc];
__device__ float g_qkv [3*MROWS*Cc];
__device__ float g_attn[MROWS*Cc];
__device__ float g_tmp [MROWS*Cc];
__device__ float g_tgt1[MROWS*Cc];
__device__ float g_tgt2[MROWS*Cc];
__device__ float g_off [MROWS*Cc];
__device__ float g_aw  [MROWS*128];
__device__ float g_val [VROWS*Cc];
__device__ float g_ffn [MROWS*DFF];

// ---------------- elementwise add ------------------------------------------
__global__ void add_kernel(const float* __restrict__ a, const float* __restrict__ b,
                           float* __restrict__ y, int n)
{
    int i = blockIdx.x * 256 + threadIdx.x;
    if (i < n) y[i] = a[i] + b[i];
}

// ---------------- tf32 tensor-core GEMM, 4-stage cp.async pipeline ----------
// Y[M,N] = X[M,K] @ W[N,K]^T + bias. Block tile 128 x BN, 256 thr (8 warps,
// 2x4). Warp tile 64 x BN/4. Raw fp32 bits as tf32 operands.
// mode 0: plain. mode 1: QKV batch over z (z picks 256-row weight block, bias,
// output slice; z==2 uses Xalt). mode 2: off/aw pair (z==1 -> W2/b2/Y2/N2,
// CTAs with x>=2 exit).
#define GP 36
template<int K, int BN>
__global__ __launch_bounds__(256, 1)
void gemm_tc(const float* __restrict__ X, const float* __restrict__ Xalt,
             const float* __restrict__ W, const float* __restrict__ bias,
             float* __restrict__ Y, int M, int N, int relu, int mode,
             const float* __restrict__ W2, const float* __restrict__ b2,
             float* __restrict__ Y2, int N2)
{
    extern __shared__ float smem[];
    constexpr int NT = BN / 32;
    constexpr int XTILE_F = 128 * GP;
    constexpr int WTILE_F = BN * GP;
    constexpr int STAGE = XTILE_F + WTILE_F;
    constexpr int NS = K >> 5;
    constexpr int TPR = 256 / BN;
    constexpr int WG  = (32 / TPR) / 4;

    const int z = blockIdx.z;
    if (mode == 1 && z) {
        W    += (size_t)z * 256 * K;
        bias += z * 256;
        Y    += (size_t)z * M * N;
        if (z == 2) X = Xalt;
    } else if (mode == 2 && z) {
        if (blockIdx.x >= 2) return;
        W = W2; bias = b2; Y = Y2; N = N2;
    }

    const int t    = threadIdx.x;
    const int warp = t >> 5;
    const int lane = t & 31;
    const int g    = lane >> 2;
    const int tg   = lane & 3;
    const int warp_m = warp >> 2;
    const int warp_n = warp & 3;
    const int m0 = blockIdx.y * 128;
    const int n0 = blockIdx.x * BN;

    const int xrow = t >> 1;
    const int xcol = (t & 1) * 16;
    const int wrow = t / TPR;
    const int wcol = (t % TPR) * (32 / TPR);

    float c[4][NT][4];
#pragma unroll
    for (int i = 0; i < 4; i++)
#pragma unroll
        for (int j = 0; j < NT; j++)
#pragma unroll
            for (int r = 0; r < 4; r++) c[i][j][r] = 0.f;

    auto prefetch = [&](int s) {
        const int k0 = s << 5;
        float* xs = smem + (s & 3) * STAGE;
        float* ws = xs + XTILE_F;
        const float* gx = &X[(size_t)(m0 + xrow) * K + k0 + xcol];
        unsigned sx = (unsigned)__cvta_generic_to_shared(&xs[xrow * GP + xcol]);
#pragma unroll
        for (int q = 0; q < 4; q++)
            asm volatile("cp.async.cg.shared.global [%0], [%1], 16;\n"
                         :: "r"(sx + q * 16), "l"(gx + q * 4));
        const float* gw = &W[(size_t)(n0 + wrow) * K + k0 + wcol];
        unsigned sw = (unsigned)__cvta_generic_to_shared(&ws[wrow * GP + wcol]);
#pragma unroll
        for (int q = 0; q < WG; q++)
            asm volatile("cp.async.cg.shared.global [%0], [%1], 16;\n"
                         :: "r"(sw + q * 16), "l"(gw + q * 4));
        asm volatile("cp.async.commit_group;\n");
    };

    prefetch(0);
    prefetch(1);
    prefetch(2);

#pragma unroll
    for (int s = 0; s < NS; s++) {
        if (s < NS - 2)       asm volatile("cp.async.wait_group 2;\n");
        else if (s == NS - 2) asm volatile("cp.async.wait_group 1;\n");
        else                  asm volatile("cp.async.wait_group 0;\n");
        __syncthreads();                 // all warps done with buf (s+3)&3
        if (s + 3 < NS) prefetch(s + 3);

        const float* xs = smem + (s & 3) * STAGE;
        const float* ws = xs + XTILE_F;

#pragma unroll
        for (int ks = 0; ks < 4; ks++) {
            const int kk = ks * 8;
            unsigned a[4][4], b[NT][2];
#pragma unroll
            for (int mt = 0; mt < 4; mt++) {
                int rb = warp_m * 64 + mt * 16;
                a[mt][0] = __float_as_uint(xs[(rb + g    ) * GP + kk + tg    ]);
                a[mt][1] = __float_as_uint(xs[(rb + g + 8) * GP + kk + tg    ]);
                a[mt][2] = __float_as_uint(xs[(rb + g    ) * GP + kk + tg + 4]);
                a[mt][3] = __float_as_uint(xs[(rb + g + 8) * GP + kk + tg + 4]);
            }
#pragma unroll
            for (int nt = 0; nt < NT; nt++) {
                int nb = warp_n * (BN / 4) + nt * 8 + g;
                b[nt][0] = __float_as_uint(ws[nb * GP + kk + tg    ]);
                b[nt][1] = __float_as_uint(ws[nb * GP + kk + tg + 4]);
            }
#pragma unroll
            for (int mt = 0; mt < 4; mt++)
#pragma unroll
                for (int nt = 0; nt < NT; nt++) {
                    asm volatile(
                        "mma.sync.aligned.m16n8k8.row.col.f32.tf32.tf32.f32 "
                        "{%0,%1,%2,%3}, {%4,%5,%6,%7}, {%8,%9}, {%0,%1,%2,%3};"
                        : "+f"(c[mt][nt][0]), "+f"(c[mt][nt][1]),
                          "+f"(c[mt][nt][2]), "+f"(c[mt][nt][3])
                        : "r"(a[mt][0]), "r"(a[mt][1]), "r"(a[mt][2]), "r"(a[mt][3]),
                          "r"(b[nt][0]), "r"(b[nt][1]));
                }
        }
    }

#pragma unroll
    for (int mt = 0; mt < 4; mt++) {
#pragma unroll
        for (int nt = 0; nt < NT; nt++) {
            int col = n0 + warp_n * (BN / 4) + nt * 8 + 2 * tg;
            float b0 = bias[col], b1 = bias[col + 1];
            int r0 = m0 + warp_m * 64 + mt * 16 + g;
            float v0 = c[mt][nt][0] + b0;
            float v1 = c[mt][nt][1] + b1;
            float v2 = c[mt][nt][2] + b0;
            float v3 = c[mt][nt][3] + b1;
            if (relu) {
                v0 = fmaxf(v0, 0.f); v1 = fmaxf(v1, 0.f);
                v2 = fmaxf(v2, 0.f); v3 = fmaxf(v3, 0.f);
            }
            Y[(size_t)r0 * N + col]           = v0;
            Y[(size_t)r0 * N + col + 1]       = v1;
            Y[(size_t)(r0 + 8) * N + col]     = v2;
            Y[(size_t)(r0 + 8) * N + col + 1] = v3;
        }
    }
}

#define SMEMB(BN) (4 * (128 + (BN)) * GP * 4)

// ---------------- residual + LayerNorm (row = 256) --------------------------
// If qpos != nullptr, also writes Yq = Y + qpos.
__global__ void add_ln_kernel(const float* __restrict__ A, const float* __restrict__ Bv,
                              const float* __restrict__ g, const float* __restrict__ be,
                              const float* __restrict__ qpos,
                              float* __restrict__ Y, float* __restrict__ Yq)
{
    int row = blockIdx.x, t = threadIdx.x;
    float x = A[(size_t)row * Cc + t] + Bv[(size_t)row * Cc + t];
    float s = x, s2 = x * x;
#pragma unroll
    for (int o = 16; o > 0; o >>= 1) {
        s  += __shfl_xor_sync(0xffffffffu, s, o);
        s2 += __shfl_xor_sync(0xffffffffu, s2, o);
    }
    __shared__ float ss[8], ss2[8];
    int w = t >> 5;
    if ((t & 31) == 0) { ss[w] = s; ss2[w] = s2; }
    __syncthreads();
    s = 0.f; s2 = 0.f;
#pragma unroll
    for (int i = 0; i < 8; i++) { s += ss[i]; s2 += ss2[i]; }
    float mean = s * (1.f / Cc);
    float var  = s2 * (1.f / Cc) - mean * mean;
    float inv  = rsqrtf(var + 1e-5f);
    float y = (x - mean) * inv * g[t] + be[t];
    Y[(size_t)row * Cc + t] = y;
    if (qpos) Yq[(size_t)row * Cc + t] = y + qpos[(size_t)row * Cc + t];
}

// ---------------- MHA attention: 64 queries / block --------------------------
__global__ __launch_bounds__(256)
void attn_kernel(const float* __restrict__ Q, const float* __restrict__ K,
                 const float* __restrict__ V, float* __restrict__ O)
{
    __shared__ float Ks[64 * 32];
    __shared__ float Vs[64 * 32];

    const int t = threadIdx.x;
    const int warp = t >> 5, lane = t & 31;
    const int quad = lane & 3, qi = lane >> 2;
    const int bh = blockIdx.y;
    const int b = bh >> 3, h = bh & 7;
    const int q = blockIdx.x * 64 + warp * 8 + qi;
    const size_t qrow = (size_t)(b * LQ + q) * Cc + h * DH;

    float qreg[32];
#pragma unroll
    for (int d4 = 0; d4 < 8; d4++) {
        float4 v4 = *(const float4*)&Q[qrow + d4 * 4];
        qreg[d4*4+0] = v4.x * 0.17677669529663687f;
        qreg[d4*4+1] = v4.y * 0.17677669529663687f;
        qreg[d4*4+2] = v4.z * 0.17677669529663687f;
        qreg[d4*4+3] = v4.w * 0.17677669529663687f;
    }

    float m = -1e30f, l = 0.f;
    float acc[8];
#pragma unroll
    for (int i = 0; i < 8; i++) acc[i] = 0.f;

    for (int c0 = 0; c0 < LQ; c0 += 64) {
        __syncthreads();
#pragma unroll
        for (int j = 0; j < 2; j++) {
            int gl = t * 2 + j;
            int row = gl >> 3, g = gl & 7;
            int gsw = g ^ ((row >> 4) & 3);
            size_t srcoff = (size_t)(b * LQ + c0 + row) * Cc + h * DH + g * 4;
            *(float4*)&Ks[row * 32 + gsw * 4] = *(const float4*)&K[srcoff];
            *(float4*)&Vs[row * 32 + gsw * 4] = *(const float4*)&V[srcoff];
        }
        __syncthreads();

        float p[16];
        float mx = -1e30f;
#pragma unroll
        for (int i = 0; i < 16; i++) {
            const int k = quad * 16 + i;
            const float* kr = Ks + k * 32;
            float s = 0.f;
#pragma unroll
            for (int g = 0; g < 8; g++) {
                float4 kv = *(const float4*)(kr + ((g ^ quad) << 2));
                s += qreg[g*4+0] * kv.x + qreg[g*4+1] * kv.y
                   + qreg[g*4+2] * kv.z + qreg[g*4+3] * kv.w;
            }
            p[i] = s;
            mx = fmaxf(mx, s);
        }
        mx = fmaxf(mx, __shfl_xor_sync(0xffffffffu, mx, 1));
        mx = fmaxf(mx, __shfl_xor_sync(0xffffffffu, mx, 2));
        float mnew = fmaxf(m, mx);
        float corr = __expf(m - mnew);
        l *= corr;
#pragma unroll
        for (int i = 0; i < 8; i++) acc[i] *= corr;
#pragma unroll
        for (int i = 0; i < 16; i++) { p[i] = __expf(p[i] - mnew); l += p[i]; }
        m = mnew;

#pragma unroll
        for (int kk = 0; kk < 64; kk++) {
            float pv = __shfl_sync(0xffffffffu, p[kk & 15], kk >> 4, 4);
            const float* vr = Vs + kk * 32;
            const int sw = (kk >> 4) & 3;
            float4 v0 = *(const float4*)(vr + (((quad * 2    ) ^ sw) << 2));
            float4 v1 = *(const float4*)(vr + (((quad * 2 + 1) ^ sw) << 2));
            acc[0] += pv * v0.x; acc[1] += pv * v0.y;
            acc[2] += pv * v0.z; acc[3] += pv * v0.w;
            acc[4] += pv * v1.x; acc[5] += pv * v1.y;
            acc[6] += pv * v1.z; acc[7] += pv * v1.w;
        }
    }

    l += __shfl_xor_sync(0xffffffffu, l, 1);
    l += __shfl_xor_sync(0xffffffffu, l, 2);
    float inv = 1.f / l;

    float4 o0 = make_float4(acc[0]*inv, acc[1]*inv, acc[2]*inv, acc[3]*inv);
    float4 o1 = make_float4(acc[4]*inv, acc[5]*inv, acc[6]*inv, acc[7]*inv);
    *(float4*)&O[qrow + quad * 8    ] = o0;
    *(float4*)&O[qrow + quad * 8 + 4] = o1;
}

// ---------------- deformable sampling (warp per (b,q,h), lane = channel) ----
__global__ void deform_kernel(const float* __restrict__ val, const float* __restrict__ offs,
                              const float* __restrict__ awl, const float* __restrict__ ref,
                              float* __restrict__ out)
{
    const int gid  = blockIdx.x * 4 + (threadIdx.x >> 5);
    const int lane = threadIdx.x & 31;
    const int h   = gid & 7;
    const int row = gid >> 3;
    const int b   = row >> 10;

    float a[16];
    float mx = -1e30f;
#pragma unroll
    for (int i = 0; i < 16; i++) {
        a[i] = awl[(size_t)row * 128 + h * 16 + i];
        mx = fmaxf(mx, a[i]);
    }
    float ssum = 0.f;
#pragma unroll
    for (int i = 0; i < 16; i++) { a[i] = __expf(a[i] - mx); ssum += a[i]; }
    float invs = 1.f / ssum;

    const int starts[4] = {0, 16384, 20480, 21504};
    float acc = 0.f;
#pragma unroll
    for (int lvl = 0; lvl < 4; lvl++) {
        const int Wl = 128 >> lvl;
        const int Hl = 128 >> lvl;
        const int start = starts[lvl];
        float rx = ref[((size_t)row * 4 + lvl) * 2 + 0];
        float ry = ref[((size_t)row * 4 + lvl) * 2 + 1];
#pragma unroll
        for (int p = 0; p < 4; p++) {
            size_t obase = (size_t)row * 256 + (((h * 4 + lvl) * 4 + p) * 2);
            float ox = offs[obase + 0];
            float oy = offs[obase + 1];
            float x = rx * (float)Wl + ox - 0.5f;
            float y = ry * (float)Hl + oy - 0.5f;
            float xf = floorf(x), yf = floorf(y);
            int x0 = (int)xf, y0 = (int)yf;
            float wx1 = x - xf, wx0 = 1.f - wx1;
            float wy1 = y - yf, wy0 = 1.f - wy1;
            float aw = a[lvl * 4 + p] * invs;

            float w00 = wx0 * wy0 * aw, w10 = wx1 * wy0 * aw;
            float w01 = wx0 * wy1 * aw, w11 = wx1 * wy1 * aw;
#pragma unroll
            for (int cidx = 0; cidx < 4; cidx++) {
                int ix = x0 + (cidx & 1);
                int iy = y0 + (cidx >> 1);
                float w = (cidx == 0) ? w00 : (cidx == 1) ? w10 : (cidx == 2) ? w01 : w11;
                if (ix >= 0 && ix < Wl && iy >= 0 && iy < Hl) {
                    size_t idx = (size_t)(b * LSRC + start + iy * Wl + ix) * Cc + h * DH + lane;
                    acc += w * val[idx];
                }
            }
        }
    }
    out[(size_t)row * Cc + h * DH + lane] = acc;
}

// ---------------- launcher ---------------------------------------------------
extern "C" void kernel_launch(void* const* d_in, const int* in_sizes, int n_in,
                              void* d_out, int out_size)
{
    const float* tgt   = (const float*)d_in[0];
    const float* qpos  = (const float*)d_in[1];
    const float* refp  = (const float*)d_in[2];
    const float* src   = (const float*)d_in[3];
    const float* in_w  = (const float*)d_in[4];
    const float* in_b  = (const float*)d_in[5];
    const float* sa_w  = (const float*)d_in[6];
    const float* sa_b  = (const float*)d_in[7];
    const float* off_w = (const float*)d_in[8];
    const float* off_b = (const float*)d_in[9];
    const float* aw_w  = (const float*)d_in[10];
    const float* aw_b  = (const float*)d_in[11];
    const float* val_w = (const float*)d_in[12];
    const float* val_b = (const float*)d_in[13];
    const float* co_w  = (const float*)d_in[14];
    const float* co_b  = (const float*)d_in[15];
    const float* ln1_g = (const float*)d_in[16];
    const float* ln1_b = (const float*)d_in[17];
    const float* ln2_g = (const float*)d_in[18];
    const float* ln2_b = (const float*)d_in[19];
    const float* ln3_g = (const float*)d_in[20];
    const float* ln3_b = (const float*)d_in[21];
    const float* f1_w  = (const float*)d_in[22];
    const float* f1_b  = (const float*)d_in[23];
    const float* f2_w  = (const float*)d_in[24];
    const float* f2_b  = (const float*)d_in[25];
    float* out = (float*)d_out;

    float *qk, *qk2, *qkv, *attn, *tmp, *t1, *t2, *off, *aw, *val, *ffn;
    cudaGetSymbolAddress((void**)&qk,   g_qk);
    cudaGetSymbolAddress((void**)&qk2,  g_qk2);
    cudaGetSymbolAddress((void**)&qkv,  g_qkv);
    cudaGetSymbolAddress((void**)&attn, g_attn);
    cudaGetSymbolAddress((void**)&tmp,  g_tmp);
    cudaGetSymbolAddress((void**)&t1,   g_tgt1);
    cudaGetSymbolAddress((void**)&t2,   g_tgt2);
    cudaGetSymbolAddress((void**)&off,  g_off);
    cudaGetSymbolAddress((void**)&aw,   g_aw);
    cudaGetSymbolAddress((void**)&val,  g_val);
    cudaGetSymbolAddress((void**)&ffn,  g_ffn);

    static cudaStream_t s1;
    static cudaEvent_t evFork, evJoin;
    static int inited = 0;
    if (!inited) {
        cudaStreamCreateWithFlags(&s1, cudaStreamNonBlocking);
        cudaEventCreateWithFlags(&evFork, cudaEventDisableTiming);
        cudaEventCreateWithFlags(&evJoin, cudaEventDisableTiming);
        cudaFuncSetAttribute(gemm_tc<256,64>,
                             cudaFuncAttributeMaxDynamicSharedMemorySize, SMEMB(64));
        cudaFuncSetAttribute(gemm_tc<256,128>,
                             cudaFuncAttributeMaxDynamicSharedMemorySize, SMEMB(128));
        cudaFuncSetAttribute(gemm_tc<1024,64>,
                             cudaFuncAttributeMaxDynamicSharedMemorySize, SMEMB(64));
        inited = 1;
    }

    const int NTOT = MROWS * Cc;

    // 1) qk = tgt + query_pos
    add_kernel<<<(NTOT + 255) / 256, 256>>>(tgt, qpos, qk, NTOT);

    // fork: value projection on side stream (depends only on src)
    cudaEventRecord(evFork, 0);
    cudaStreamWaitEvent(s1, evFork, 0);
    gemm_tc<256,128><<<dim3(2, VROWS / 128), 256, SMEMB(128), s1>>>(
        src, nullptr, val_w, val_b, val, VROWS, Cc, 0, 0,
        nullptr, nullptr, nullptr, 0);
    cudaEventRecord(evJoin, s1);

    // 2) Q/K/V projections — batched over grid.z (z==2 uses tgt)
    gemm_tc<256,64><<<dim3(4, 32, 3), 256, SMEMB(64)>>>(
        qk, tgt, in_w, in_b, qkv, MROWS, Cc, 0, 1,
        nullptr, nullptr, nullptr, 0);

    // 3) attention
    attn_kernel<<<dim3(LQ / 64, Bz * Hh), 256>>>(
        qkv, qkv + MROWS * Cc, qkv + 2 * MROWS * Cc, attn);

    // 4) self-attn out proj + residual + LN(ln2) -> t1, and qk2 = t1 + qpos
    gemm_tc<256,64><<<dim3(4, 32), 256, SMEMB(64)>>>(
        attn, nullptr, sa_w, sa_b, tmp, MROWS, Cc, 0, 0,
        nullptr, nullptr, nullptr, 0);
    add_ln_kernel<<<MROWS, 256>>>(tgt, tmp, ln2_g, ln2_b, qpos, t1, qk2);

    // 5+6) offsets + attention weights in one z-batched launch
    gemm_tc<256,64><<<dim3(4, 32, 2), 256, SMEMB(64)>>>(
        qk2, nullptr, off_w, off_b, off, MROWS, Cc, 0, 2,
        aw_w, aw_b, aw, 128);

    // join value projection, then deformable sampling
    cudaStreamWaitEvent(0, evJoin, 0);
    deform_kernel<<<(MROWS * Hh) / 4, 128>>>(val, off, aw, refp, attn);

    // 8) co proj + residual + LN(ln1) -> t2
    gemm_tc<256,64><<<dim3(4, 32), 256, SMEMB(64)>>>(
        attn, nullptr, co_w, co_b, tmp, MROWS, Cc, 0, 0,
        nullptr, nullptr, nullptr, 0);
    add_ln_kernel<<<MROWS, 256>>>(t1, tmp, ln1_g, ln1_b, nullptr, t2, nullptr);

    // 9) FFN + residual + LN(ln3) -> out
    gemm_tc<256,64><<<dim3(16, 32), 256, SMEMB(64)>>>(
        t2, nullptr, f1_w, f1_b, ffn, MROWS, DFF, 1, 0,
        nullptr, nullptr, nullptr, 0);
    gemm_tc<1024,64><<<dim3(4, 32), 256, SMEMB(64)>>>(
        ffn, nullptr, f2_w, f2_b, tmp, MROWS, Cc, 0, 0,
        nullptr, nullptr, nullptr, 0);
    add_ln_kernel<<<MROWS, 256>>>(t2, tmp, ln3_g, ln3_b, nullptr, out, nullptr);
}

// round 8
// speedup vs baseline: 3.9029x; 1.0838x over previous
#include <cuda_runtime.h>
#include <cuda_bf16.h>
#include <math.h>

#define Bz   4
#define LQ   1024
#define Cc   256
#define Hh   8
#define DH   32
#define DFF  1024
#define LSRC 21760
#define MROWS (Bz*LQ)        // 4096
#define VROWS (Bz*LSRC)      // 87040

// ---------------- scratch (static device globals) ---------------------------
__device__ float g_qk  [MROWS*Cc];
__device__ float g_qk2 [MROWS*Cc];
__device__ float g_qkv [3*MROWS*Cc];
__device__ float g_attn[MROWS*Cc];
__device__ float g_tmp [MROWS*Cc];
__device__ float g_tgt1[MROWS*Cc];
__device__ float g_tgt2[MROWS*Cc];
__device__ float g_off [MROWS*Cc];
__device__ float g_aw  [MROWS*128];
__device__ float g_val [VROWS*Cc];
__device__ float g_ffn [MROWS*DFF];

__device__ __forceinline__ unsigned rna_tf32(float x) {
    unsigned r;
    asm("cvt.rna.tf32.f32 %0, %1;" : "=r"(r) : "f"(x));
    return r;
}

#define MMA_TF32(C, A0,A1,A2,A3, B0,B1) \
    asm volatile("mma.sync.aligned.m16n8k8.row.col.f32.tf32.tf32.f32 " \
                 "{%0,%1,%2,%3}, {%4,%5,%6,%7}, {%8,%9}, {%0,%1,%2,%3};" \
                 : "+f"(C[0]), "+f"(C[1]), "+f"(C[2]), "+f"(C[3]) \
                 : "r"(A0), "r"(A1), "r"(A2), "r"(A3), "r"(B0), "r"(B1))

// ---------------- elementwise add ------------------------------------------
__global__ void add_kernel(const float* __restrict__ a, const float* __restrict__ b,
                           float* __restrict__ y, int n)
{
    int i = blockIdx.x * 256 + threadIdx.x;
    if (i < n) y[i] = a[i] + b[i];
}

// ---------------- tf32 tensor-core GEMM, 4-stage cp.async pipeline ----------
#define GP 36
template<int K, int BN>
__global__ __launch_bounds__(256, 1)
void gemm_tc(const float* __restrict__ X, const float* __restrict__ Xalt,
             const float* __restrict__ W, const float* __restrict__ bias,
             float* __restrict__ Y, int M, int N, int relu, int mode,
             const float* __restrict__ W2, const float* __restrict__ b2,
             float* __restrict__ Y2, int N2)
{
    extern __shared__ float smem[];
    constexpr int NT = BN / 32;
    constexpr int XTILE_F = 128 * GP;
    constexpr int WTILE_F = BN * GP;
    constexpr int STAGE = XTILE_F + WTILE_F;
    constexpr int NS = K >> 5;
    constexpr int TPR = 256 / BN;
    constexpr int WG  = (32 / TPR) / 4;

    const int z = blockIdx.z;
    if (mode == 1 && z) {
        W    += (size_t)z * 256 * K;
        bias += z * 256;
        Y    += (size_t)z * M * N;
        if (z == 2) X = Xalt;
    } else if (mode == 2 && z) {
        if (blockIdx.x >= 2) return;
        W = W2; bias = b2; Y = Y2; N = N2;
    }

    const int t    = threadIdx.x;
    const int warp = t >> 5;
    const int lane = t & 31;
    const int g    = lane >> 2;
    const int tg   = lane & 3;
    const int warp_m = warp >> 2;
    const int warp_n = warp & 3;
    const int m0 = blockIdx.y * 128;
    const int n0 = blockIdx.x * BN;

    const int xrow = t >> 1;
    const int xcol = (t & 1) * 16;
    const int wrow = t / TPR;
    const int wcol = (t % TPR) * (32 / TPR);

    float c[4][NT][4];
#pragma unroll
    for (int i = 0; i < 4; i++)
#pragma unroll
        for (int j = 0; j < NT; j++)
#pragma unroll
            for (int r = 0; r < 4; r++) c[i][j][r] = 0.f;

    auto prefetch = [&](int s) {
        const int k0 = s << 5;
        float* xs = smem + (s & 3) * STAGE;
        float* ws = xs + XTILE_F;
        const float* gx = &X[(size_t)(m0 + xrow) * K + k0 + xcol];
        unsigned sx = (unsigned)__cvta_generic_to_shared(&xs[xrow * GP + xcol]);
#pragma unroll
        for (int q = 0; q < 4; q++)
            asm volatile("cp.async.cg.shared.global [%0], [%1], 16;\n"
                         :: "r"(sx + q * 16), "l"(gx + q * 4));
        const float* gw = &W[(size_t)(n0 + wrow) * K + k0 + wcol];
        unsigned sw = (unsigned)__cvta_generic_to_shared(&ws[wrow * GP + wcol]);
#pragma unroll
        for (int q = 0; q < WG; q++)
            asm volatile("cp.async.cg.shared.global [%0], [%1], 16;\n"
                         :: "r"(sw + q * 16), "l"(gw + q * 4));
        asm volatile("cp.async.commit_group;\n");
    };

    prefetch(0);
    prefetch(1);
    prefetch(2);

#pragma unroll
    for (int s = 0; s < NS; s++) {
        if (s < NS - 2)       asm volatile("cp.async.wait_group 2;\n");
        else if (s == NS - 2) asm volatile("cp.async.wait_group 1;\n");
        else                  asm volatile("cp.async.wait_group 0;\n");
        __syncthreads();
        if (s + 3 < NS) prefetch(s + 3);

        const float* xs = smem + (s & 3) * STAGE;
        const float* ws = xs + XTILE_F;

#pragma unroll
        for (int ks = 0; ks < 4; ks++) {
            const int kk = ks * 8;
            unsigned a[4][4], b[NT][2];
#pragma unroll
            for (int mt = 0; mt < 4; mt++) {
                int rb = warp_m * 64 + mt * 16;
                a[mt][0] = __float_as_uint(xs[(rb + g    ) * GP + kk + tg    ]);
                a[mt][1] = __float_as_uint(xs[(rb + g + 8) * GP + kk + tg    ]);
                a[mt][2] = __float_as_uint(xs[(rb + g    ) * GP + kk + tg + 4]);
                a[mt][3] = __float_as_uint(xs[(rb + g + 8) * GP + kk + tg + 4]);
            }
#pragma unroll
            for (int nt = 0; nt < NT; nt++) {
                int nb = warp_n * (BN / 4) + nt * 8 + g;
                b[nt][0] = __float_as_uint(ws[nb * GP + kk + tg    ]);
                b[nt][1] = __float_as_uint(ws[nb * GP + kk + tg + 4]);
            }
#pragma unroll
            for (int mt = 0; mt < 4; mt++)
#pragma unroll
                for (int nt = 0; nt < NT; nt++)
                    MMA_TF32(c[mt][nt], a[mt][0], a[mt][1], a[mt][2], a[mt][3],
                             b[nt][0], b[nt][1]);
        }
    }

#pragma unroll
    for (int mt = 0; mt < 4; mt++) {
#pragma unroll
        for (int nt = 0; nt < NT; nt++) {
            int col = n0 + warp_n * (BN / 4) + nt * 8 + 2 * tg;
            float b0 = bias[col], b1 = bias[col + 1];
            int r0 = m0 + warp_m * 64 + mt * 16 + g;
            float v0 = c[mt][nt][0] + b0;
            float v1 = c[mt][nt][1] + b1;
            float v2 = c[mt][nt][2] + b0;
            float v3 = c[mt][nt][3] + b1;
            if (relu) {
                v0 = fmaxf(v0, 0.f); v1 = fmaxf(v1, 0.f);
                v2 = fmaxf(v2, 0.f); v3 = fmaxf(v3, 0.f);
            }
            Y[(size_t)r0 * N + col]           = v0;
            Y[(size_t)r0 * N + col + 1]       = v1;
            Y[(size_t)(r0 + 8) * N + col]     = v2;
            Y[(size_t)(r0 + 8) * N + col + 1] = v3;
        }
    }
}

#define SMEMB(BN) (4 * (128 + (BN)) * GP * 4)

// ---------------- residual + LayerNorm (row = 256) --------------------------
__global__ void add_ln_kernel(const float* __restrict__ A, const float* __restrict__ Bv,
                              const float* __restrict__ g, const float* __restrict__ be,
                              const float* __restrict__ qpos,
                              float* __restrict__ Y, float* __restrict__ Yq)
{
    int row = blockIdx.x, t = threadIdx.x;
    float x = A[(size_t)row * Cc + t] + Bv[(size_t)row * Cc + t];
    float s = x, s2 = x * x;
#pragma unroll
    for (int o = 16; o > 0; o >>= 1) {
        s  += __shfl_xor_sync(0xffffffffu, s, o);
        s2 += __shfl_xor_sync(0xffffffffu, s2, o);
    }
    __shared__ float ss[8], ss2[8];
    int w = t >> 5;
    if ((t & 31) == 0) { ss[w] = s; ss2[w] = s2; }
    __syncthreads();
    s = 0.f; s2 = 0.f;
#pragma unroll
    for (int i = 0; i < 8; i++) { s += ss[i]; s2 += ss2[i]; }
    float mean = s * (1.f / Cc);
    float var  = s2 * (1.f / Cc) - mean * mean;
    float inv  = rsqrtf(var + 1e-5f);
    float y = (x - mean) * inv * g[t] + be[t];
    Y[(size_t)row * Cc + t] = y;
    if (qpos) Yq[(size_t)row * Cc + t] = y + qpos[(size_t)row * Cc + t];
}

// ---------------- tensor-core flash attention -------------------------------
// grid (LQ/128, B*H), 256 thr (8 warps). Warp owns 16 query rows -> softmax
// rows never cross warps. K chunk [64][36], V transposed Vt[32][68] in smem;
// all fragment LDS addresses hash to bank = lane (conflict-free).
#define KP 36
#define VP 68
__global__ __launch_bounds__(256, 2)
void attn_kernel(const float* __restrict__ Q, const float* __restrict__ K,
                 const float* __restrict__ V, float* __restrict__ O)
{
    __shared__ float Qs[128 * KP];
    __shared__ float Ks[64 * KP];
    __shared__ float Vt[32 * VP];

    const int t = threadIdx.x;
    const int warp = t >> 5, lane = t & 31;
    const int g = lane >> 2, tg = lane & 3;
    const int bh = blockIdx.y;
    const int b = bh >> 3, h = bh & 7;
    const int q0 = blockIdx.x * 128;
    const size_t base = ((size_t)b * LQ) * Cc + h * DH;

    // stage Q (scaled) into smem
#pragma unroll
    for (int j = 0; j < 4; j++) {
        int idx = j * 256 + t;
        int row = idx >> 3, c4 = (idx & 7) * 4;
        float4 v4 = *(const float4*)&Q[base + (size_t)(q0 + row) * Cc + c4];
        v4.x *= 0.17677669529663687f; v4.y *= 0.17677669529663687f;
        v4.z *= 0.17677669529663687f; v4.w *= 0.17677669529663687f;
        *(float4*)&Qs[row * KP + c4] = v4;
    }
    __syncthreads();

    // Q fragments (row r = warp*16+g / +8), 4 k-tiles over dh=32
    unsigned qa[4][4];
    {
        int r = warp * 16 + g;
#pragma unroll
        for (int kt = 0; kt < 4; kt++) {
            qa[kt][0] = __float_as_uint(Qs[r * KP + kt * 8 + tg]);
            qa[kt][1] = __float_as_uint(Qs[(r + 8) * KP + kt * 8 + tg]);
            qa[kt][2] = __float_as_uint(Qs[r * KP + kt * 8 + tg + 4]);
            qa[kt][3] = __float_as_uint(Qs[(r + 8) * KP + kt * 8 + tg + 4]);
        }
    }

    float o[4][4];
#pragma unroll
    for (int nt = 0; nt < 4; nt++)
#pragma unroll
        for (int r = 0; r < 4; r++) o[nt][r] = 0.f;
    float m0 = -1e30f, m1 = -1e30f, l0 = 0.f, l1 = 0.f;

    for (int c0 = 0; c0 < LQ; c0 += 64) {
        __syncthreads();
        // K chunk: straight copy
#pragma unroll
        for (int j = 0; j < 2; j++) {
            int idx = j * 256 + t;
            int row = idx >> 3, c4 = (idx & 7) * 4;
            *(float4*)&Ks[row * KP + c4] =
                *(const float4*)&K[base + (size_t)(c0 + row) * Cc + c4];
        }
        // V chunk: transpose into Vt[d][key], rna-rounded to tf32
        {
            int key = t & 63, dg = t >> 6;
#pragma unroll
            for (int jj = 0; jj < 2; jj++) {
                float4 v4 = *(const float4*)&V[base + (size_t)(c0 + key) * Cc + dg * 8 + jj * 4];
                Vt[(dg * 8 + jj * 4 + 0) * VP + key] = __uint_as_float(rna_tf32(v4.x));
                Vt[(dg * 8 + jj * 4 + 1) * VP + key] = __uint_as_float(rna_tf32(v4.y));
                Vt[(dg * 8 + jj * 4 + 2) * VP + key] = __uint_as_float(rna_tf32(v4.z));
                Vt[(dg * 8 + jj * 4 + 3) * VP + key] = __uint_as_float(rna_tf32(v4.w));
            }
        }
        __syncthreads();

        // S = Q @ K^T : 8 n-tiles (64 keys) x 4 k-tiles (dh)
        float c[8][4];
#pragma unroll
        for (int nt = 0; nt < 8; nt++)
#pragma unroll
            for (int r = 0; r < 4; r++) c[nt][r] = 0.f;
#pragma unroll
        for (int kt = 0; kt < 4; kt++) {
#pragma unroll
            for (int nt = 0; nt < 8; nt++) {
                unsigned b0 = __float_as_uint(Ks[(nt * 8 + g) * KP + kt * 8 + tg]);
                unsigned b1 = __float_as_uint(Ks[(nt * 8 + g) * KP + kt * 8 + tg + 4]);
                MMA_TF32(c[nt], qa[kt][0], qa[kt][1], qa[kt][2], qa[kt][3], b0, b1);
            }
        }

        // online softmax on fragments (rows g and g+8)
        float mx0 = -1e30f, mx1 = -1e30f;
#pragma unroll
        for (int nt = 0; nt < 8; nt++) {
            mx0 = fmaxf(mx0, fmaxf(c[nt][0], c[nt][1]));
            mx1 = fmaxf(mx1, fmaxf(c[nt][2], c[nt][3]));
        }
        mx0 = fmaxf(mx0, __shfl_xor_sync(0xffffffffu, mx0, 1));
        mx0 = fmaxf(mx0, __shfl_xor_sync(0xffffffffu, mx0, 2));
        mx1 = fmaxf(mx1, __shfl_xor_sync(0xffffffffu, mx1, 1));
        mx1 = fmaxf(mx1, __shfl_xor_sync(0xffffffffu, mx1, 2));
        float mn0 = fmaxf(m0, mx0), mn1 = fmaxf(m1, mx1);
        float cor0 = __expf(m0 - mn0), cor1 = __expf(m1 - mn1);
        l0 *= cor0; l1 *= cor1;
#pragma unroll
        for (int nt = 0; nt < 4; nt++) {
            o[nt][0] *= cor0; o[nt][1] *= cor0;
            o[nt][2] *= cor1; o[nt][3] *= cor1;
        }
#pragma unroll
        for (int nt = 0; nt < 8; nt++) {
            float p0 = __expf(c[nt][0] - mn0);
            float p1 = __expf(c[nt][1] - mn0);
            float p2 = __expf(c[nt][2] - mn1);
            float p3 = __expf(c[nt][3] - mn1);
            l0 += p0 + p1; l1 += p2 + p3;
            c[nt][0] = __uint_as_float(rna_tf32(p0));
            c[nt][1] = __uint_as_float(rna_tf32(p1));
            c[nt][2] = __uint_as_float(rna_tf32(p2));
            c[nt][3] = __uint_as_float(rna_tf32(p3));
        }
        m0 = mn0; m1 = mn1;

        // O += P @ V : redistribute P fragments (C-layout -> A-layout) via shfl
        const int src0 = (lane & ~3) | (tg >> 1);
        const int src2 = src0 + 2;
        const bool odd = tg & 1;
#pragma unroll
        for (int kt = 0; kt < 8; kt++) {
            float e00 = __shfl_sync(0xffffffffu, c[kt][0], src0);
            float e01 = __shfl_sync(0xffffffffu, c[kt][1], src0);
            float e10 = __shfl_sync(0xffffffffu, c[kt][2], src0);
            float e11 = __shfl_sync(0xffffffffu, c[kt][3], src0);
            float e20 = __shfl_sync(0xffffffffu, c[kt][0], src2);
            float e21 = __shfl_sync(0xffffffffu, c[kt][1], src2);
            float e30 = __shfl_sync(0xffffffffu, c[kt][2], src2);
            float e31 = __shfl_sync(0xffffffffu, c[kt][3], src2);
            unsigned a0 = __float_as_uint(odd ? e01 : e00);
            unsigned a1 = __float_as_uint(odd ? e11 : e10);
            unsigned a2 = __float_as_uint(odd ? e21 : e20);
            unsigned a3 = __float_as_uint(odd ? e31 : e30);
#pragma unroll
            for (int nt = 0; nt < 4; nt++) {
                unsigned b0 = __float_as_uint(Vt[(nt * 8 + g) * VP + kt * 8 + tg]);
                unsigned b1 = __float_as_uint(Vt[(nt * 8 + g) * VP + kt * 8 + tg + 4]);
                MMA_TF32(o[nt], a0, a1, a2, a3, b0, b1);
            }
        }
    }

    // finalize rows
    l0 += __shfl_xor_sync(0xffffffffu, l0, 1);
    l0 += __shfl_xor_sync(0xffffffffu, l0, 2);
    l1 += __shfl_xor_sync(0xffffffffu, l1, 1);
    l1 += __shfl_xor_sync(0xffffffffu, l1, 2);
    float inv0 = 1.f / l0, inv1 = 1.f / l1;

    int r0 = q0 + warp * 16 + g;
#pragma unroll
    for (int nt = 0; nt < 4; nt++) {
        int col = nt * 8 + 2 * tg;
        float2 w0 = make_float2(o[nt][0] * inv0, o[nt][1] * inv0);
        float2 w1 = make_float2(o[nt][2] * inv1, o[nt][3] * inv1);
        *(float2*)&O[base + (size_t)r0 * Cc + col]       = w0;
        *(float2*)&O[base + (size_t)(r0 + 8) * Cc + col] = w1;
    }
}

// ---------------- deformable sampling (warp per (b,q,h), lane = channel) ----
__global__ void deform_kernel(const float* __restrict__ val, const float* __restrict__ offs,
                              const float* __restrict__ awl, const float* __restrict__ ref,
                              float* __restrict__ out)
{
    const int gid  = blockIdx.x * 4 + (threadIdx.x >> 5);
    const int lane = threadIdx.x & 31;
    const int h   = gid & 7;
    const int row = gid >> 3;
    const int b   = row >> 10;

    float a[16];
    float mx = -1e30f;
#pragma unroll
    for (int i = 0; i < 16; i++) {
        a[i] = awl[(size_t)row * 128 + h * 16 + i];
        mx = fmaxf(mx, a[i]);
    }
    float ssum = 0.f;
#pragma unroll
    for (int i = 0; i < 16; i++) { a[i] = __expf(a[i] - mx); ssum += a[i]; }
    float invs = 1.f / ssum;

    const int starts[4] = {0, 16384, 20480, 21504};
    float acc = 0.f;
#pragma unroll
    for (int lvl = 0; lvl < 4; lvl++) {
        const int Wl = 128 >> lvl;
        const int Hl = 128 >> lvl;
        const int start = starts[lvl];
        float rx = ref[((size_t)row * 4 + lvl) * 2 + 0];
        float ry = ref[((size_t)row * 4 + lvl) * 2 + 1];
#pragma unroll
        for (int p = 0; p < 4; p++) {
            size_t obase = (size_t)row * 256 + (((h * 4 + lvl) * 4 + p) * 2);
            float ox = offs[obase + 0];
            float oy = offs[obase + 1];
            float x = rx * (float)Wl + ox - 0.5f;
            float y = ry * (float)Hl + oy - 0.5f;
            float xf = floorf(x), yf = floorf(y);
            int x0 = (int)xf, y0 = (int)yf;
            float wx1 = x - xf, wx0 = 1.f - wx1;
            float wy1 = y - yf, wy0 = 1.f - wy1;
            float aw = a[lvl * 4 + p] * invs;

            float w00 = wx0 * wy0 * aw, w10 = wx1 * wy0 * aw;
            float w01 = wx0 * wy1 * aw, w11 = wx1 * wy1 * aw;
#pragma unroll
            for (int cidx = 0; cidx < 4; cidx++) {
                int ix = x0 + (cidx & 1);
                int iy = y0 + (cidx >> 1);
                float w = (cidx == 0) ? w00 : (cidx == 1) ? w10 : (cidx == 2) ? w01 : w11;
                if (ix >= 0 && ix < Wl && iy >= 0 && iy < Hl) {
                    size_t idx = (size_t)(b * LSRC + start + iy * Wl + ix) * Cc + h * DH + lane;
                    acc += w * val[idx];
                }
            }
        }
    }
    out[(size_t)row * Cc + h * DH + lane] = acc;
}

// ---------------- launcher ---------------------------------------------------
extern "C" void kernel_launch(void* const* d_in, const int* in_sizes, int n_in,
                              void* d_out, int out_size)
{
    const float* tgt   = (const float*)d_in[0];
    const float* qpos  = (const float*)d_in[1];
    const float* refp  = (const float*)d_in[2];
    const float* src   = (const float*)d_in[3];
    const float* in_w  = (const float*)d_in[4];
    const float* in_b  = (const float*)d_in[5];
    const float* sa_w  = (const float*)d_in[6];
    const float* sa_b  = (const float*)d_in[7];
    const float* off_w = (const float*)d_in[8];
    const float* off_b = (const float*)d_in[9];
    const float* aw_w  = (const float*)d_in[10];
    const float* aw_b  = (const float*)d_in[11];
    const float* val_w = (const float*)d_in[12];
    const float* val_b = (const float*)d_in[13];
    const float* co_w  = (const float*)d_in[14];
    const float* co_b  = (const float*)d_in[15];
    const float* ln1_g = (const float*)d_in[16];
    const float* ln1_b = (const float*)d_in[17];
    const float* ln2_g = (const float*)d_in[18];
    const float* ln2_b = (const float*)d_in[19];
    const float* ln3_g = (const float*)d_in[20];
    const float* ln3_b = (const float*)d_in[21];
    const float* f1_w  = (const float*)d_in[22];
    const float* f1_b  = (const float*)d_in[23];
    const float* f2_w  = (const float*)d_in[24];
    const float* f2_b  = (const float*)d_in[25];
    float* out = (float*)d_out;

    float *qk, *qk2, *qkv, *attn, *tmp, *t1, *t2, *off, *aw, *val, *ffn;
    cudaGetSymbolAddress((void**)&qk,   g_qk);
    cudaGetSymbolAddress((void**)&qk2,  g_qk2);
    cudaGetSymbolAddress((void**)&qkv,  g_qkv);
    cudaGetSymbolAddress((void**)&attn, g_attn);
    cudaGetSymbolAddress((void**)&tmp,  g_tmp);
    cudaGetSymbolAddress((void**)&t1,   g_tgt1);
    cudaGetSymbolAddress((void**)&t2,   g_tgt2);
    cudaGetSymbolAddress((void**)&off,  g_off);
    cudaGetSymbolAddress((void**)&aw,   g_aw);
    cudaGetSymbolAddress((void**)&val,  g_val);
    cudaGetSymbolAddress((void**)&ffn,  g_ffn);

    static cudaStream_t s1;
    static cudaEvent_t evFork, evJoin;
    static int inited = 0;
    if (!inited) {
        cudaStreamCreateWithFlags(&s1, cudaStreamNonBlocking);
        cudaEventCreateWithFlags(&evFork, cudaEventDisableTiming);
        cudaEventCreateWithFlags(&evJoin, cudaEventDisableTiming);
        cudaFuncSetAttribute(gemm_tc<256,64>,
                             cudaFuncAttributeMaxDynamicSharedMemorySize, SMEMB(64));
        cudaFuncSetAttribute(gemm_tc<256,128>,
                             cudaFuncAttributeMaxDynamicSharedMemorySize, SMEMB(128));
        cudaFuncSetAttribute(gemm_tc<1024,64>,
                             cudaFuncAttributeMaxDynamicSharedMemorySize, SMEMB(64));
        inited = 1;
    }

    const int NTOT = MROWS * Cc;

    // 1) qk = tgt + query_pos
    add_kernel<<<(NTOT + 255) / 256, 256>>>(tgt, qpos, qk, NTOT);

    // fork: value projection on side stream (depends only on src)
    cudaEventRecord(evFork, 0);
    cudaStreamWaitEvent(s1, evFork, 0);
    gemm_tc<256,128><<<dim3(2, VROWS / 128), 256, SMEMB(128), s1>>>(
        src, nullptr, val_w, val_b, val, VROWS, Cc, 0, 0,
        nullptr, nullptr, nullptr, 0);
    cudaEventRecord(evJoin, s1);

    // 2) Q/K/V projections — batched over grid.z
    gemm_tc<256,64><<<dim3(4, 32, 3), 256, SMEMB(64)>>>(
        qk, tgt, in_w, in_b, qkv, MROWS, Cc, 0, 1,
        nullptr, nullptr, nullptr, 0);

    // 3) attention (tensor-core flash)
    attn_kernel<<<dim3(LQ / 128, Bz * Hh), 256>>>(
        qkv, qkv + MROWS * Cc, qkv + 2 * MROWS * Cc, attn);

    // 4) self-attn out proj + residual + LN(ln2) -> t1, and qk2 = t1 + qpos
    gemm_tc<256,64><<<dim3(4, 32), 256, SMEMB(64)>>>(
        attn, nullptr, sa_w, sa_b, tmp, MROWS, Cc, 0, 0,
        nullptr, nullptr, nullptr, 0);
    add_ln_kernel<<<MROWS, 256>>>(tgt, tmp, ln2_g, ln2_b, qpos, t1, qk2);

    // 5+6) offsets + attention weights in one z-batched launch
    gemm_tc<256,64><<<dim3(4, 32, 2), 256, SMEMB(64)>>>(
        qk2, nullptr, off_w, off_b, off, MROWS, Cc, 0, 2,
        aw_w, aw_b, aw, 128);

    // join value projection, then deformable sampling
    cudaStreamWaitEvent(0, evJoin, 0);
    deform_kernel<<<(MROWS * Hh) / 4, 128>>>(val, off, aw, refp, attn);

    // 8) co proj + residual + LN(ln1) -> t2
    gemm_tc<256,64><<<dim3(4, 32), 256, SMEMB(64)>>>(
        attn, nullptr, co_w, co_b, tmp, MROWS, Cc, 0, 0,
        nullptr, nullptr, nullptr, 0);
    add_ln_kernel<<<MROWS, 256>>>(t1, tmp, ln1_g, ln1_b, nullptr, t2, nullptr);

    // 9) FFN + residual + LN(ln3) -> out
    gemm_tc<256,64><<<dim3(16, 32), 256, SMEMB(64)>>>(
        t2, nullptr, f1_w, f1_b, ffn, MROWS, DFF, 1, 0,
        nullptr, nullptr, nullptr, 0);
    gemm_tc<1024,64><<<dim3(4, 32), 256, SMEMB(64)>>>(
        ffn, nullptr, f2_w, f2_b, tmp, MROWS, Cc, 0, 0,
        nullptr, nullptr, nullptr, 0);
    add_ln_kernel<<<MROWS, 256>>>(t2, tmp, ln3_g, ln3_b, nullptr, out, nullptr);
}

// round 9
// speedup vs baseline: 6.0261x; 1.5440x over previous
#include <cuda_runtime.h>
#include <cuda_bf16.h>
#include <math.h>

#define Bz   4
#define LQ   1024
#define Cc   256
#define Hh   8
#define DH   32
#define DFF  1024
#define LSRC 21760
#define MROWS (Bz*LQ)        // 4096
#define VROWS (Bz*LSRC)      // 87040

// ---------------- scratch (static device globals) ---------------------------
__device__ float g_qk  [MROWS*Cc];
__device__ float g_qk2 [MROWS*Cc];
__device__ float g_qkv [3*MROWS*Cc];
__device__ float g_attn[MROWS*Cc];
__device__ float g_tmp [MROWS*Cc];
__device__ float g_tgt1[MROWS*Cc];
__device__ float g_tgt2[MROWS*Cc];
__device__ float g_off [MROWS*Cc];
__device__ float g_aw  [MROWS*128];
__device__ float g_val [VROWS*Cc];
__device__ float g_ffn [MROWS*DFF];
__device__ float g_part[4*MROWS*Cc];
__device__ float g_zero[DFF];          // zero-initialized

__device__ __forceinline__ unsigned rna_tf32(float x) {
    unsigned r;
    asm("cvt.rna.tf32.f32 %0, %1;" : "=r"(r) : "f"(x));
    return r;
}

#define MMA_TF32(C, A0,A1,A2,A3, B0,B1) \
    asm volatile("mma.sync.aligned.m16n8k8.row.col.f32.tf32.tf32.f32 " \
                 "{%0,%1,%2,%3}, {%4,%5,%6,%7}, {%8,%9}, {%0,%1,%2,%3};" \
                 : "+f"(C[0]), "+f"(C[1]), "+f"(C[2]), "+f"(C[3]) \
                 : "r"(A0), "r"(A1), "r"(A2), "r"(A3), "r"(B0), "r"(B1))

// ---------------- elementwise add ------------------------------------------
__global__ void add_kernel(const float* __restrict__ a, const float* __restrict__ b,
                           float* __restrict__ y, int n)
{
    int i = blockIdx.x * 256 + threadIdx.x;
    if (i < n) y[i] = a[i] + b[i];
}

// ---------------- tf32 tensor-core GEMM, 2-stage, 1 barrier per K-step ------
// Y[M,N] = X[M,K(ldx)] @ W[N,K(ldw)]^T + bias. Block tile BM x BN, 256 thr
// (8 warps 2x4); warp tile BM/2 x BN/4. Raw fp32 bits as tf32 operands.
// mode 0: plain. mode 1: QKV batch over z. mode 2: off/aw pair.
// mode 3: split-K over z (X,W advance z*K cols; bias only z==0; Y partials).
#define GP 36
template<int K, int BM, int BN>
__global__ __launch_bounds__(256, 2)
void gemm_tc(const float* __restrict__ X, const float* __restrict__ Xalt,
             const float* __restrict__ W, const float* __restrict__ bias,
             float* __restrict__ Y, int M, int N, int relu, int mode,
             const float* __restrict__ W2, const float* __restrict__ b2,
             float* __restrict__ Y2, int N2, int ldx, int ldw)
{
    extern __shared__ float smem[];
    constexpr int MT = BM / 32;            // m-tile count (2 or 4)
    constexpr int NT = BN / 32;            // n-tile count
    constexpr int XTILE_F = BM * GP;
    constexpr int STAGE = (BM + BN) * GP;
    constexpr int NS = K >> 5;
    constexpr int TPRX = 256 / BM;         // threads per X row
    constexpr int XG   = (32 / TPRX) / 4;  // 16B granules / thread (X)
    constexpr int TPRW = 256 / BN;
    constexpr int WG   = (32 / TPRW) / 4;

    const int z = blockIdx.z;
    if (mode == 1 && z) {
        W    += (size_t)z * 256 * K;
        bias += z * 256;
        Y    += (size_t)z * M * N;
        if (z == 2) X = Xalt;
    } else if (mode == 2 && z) {
        if (blockIdx.x >= 2) return;
        W = W2; bias = b2; Y = Y2; N = N2;
    } else if (mode == 3) {
        X += z * K;
        W += z * K;
        Y += (size_t)z * M * N;
        if (z) bias = b2;                  // zero bias for z>0
    }

    const int t    = threadIdx.x;
    const int warp = t >> 5;
    const int lane = t & 31;
    const int g    = lane >> 2;
    const int tg   = lane & 3;
    const int warp_m = warp >> 2;
    const int warp_n = warp & 3;
    const int m0 = blockIdx.y * BM;
    const int n0 = blockIdx.x * BN;

    const int xrow = t / TPRX;
    const int xcol = (t % TPRX) * (32 / TPRX);
    const int wrow = t / TPRW;
    const int wcol = (t % TPRW) * (32 / TPRW);

    float c[MT][NT][4];
#pragma unroll
    for (int i = 0; i < MT; i++)
#pragma unroll
        for (int j = 0; j < NT; j++)
#pragma unroll
            for (int r = 0; r < 4; r++) c[i][j][r] = 0.f;

    auto prefetch = [&](int s) {
        const int k0 = s << 5;
        float* xs = smem + (s & 1) * STAGE;
        float* ws = xs + XTILE_F;
        const float* gx = &X[(size_t)(m0 + xrow) * ldx + k0 + xcol];
        unsigned sx = (unsigned)__cvta_generic_to_shared(&xs[xrow * GP + xcol]);
#pragma unroll
        for (int q = 0; q < XG; q++)
            asm volatile("cp.async.cg.shared.global [%0], [%1], 16;\n"
                         :: "r"(sx + q * 16), "l"(gx + q * 4));
        const float* gw = &W[(size_t)(n0 + wrow) * ldw + k0 + wcol];
        unsigned sw = (unsigned)__cvta_generic_to_shared(&ws[wrow * GP + wcol]);
#pragma unroll
        for (int q = 0; q < WG; q++)
            asm volatile("cp.async.cg.shared.global [%0], [%1], 16;\n"
                         :: "r"(sw + q * 16), "l"(gw + q * 4));
        asm volatile("cp.async.commit_group;\n");
    };

    prefetch(0);

#pragma unroll
    for (int s = 0; s < NS; s++) {
        asm volatile("cp.async.wait_group 0;\n");
        __syncthreads();                 // all warps done with buf (s+1)&1
        if (s + 1 < NS) prefetch(s + 1);

        const float* xs = smem + (s & 1) * STAGE;
        const float* ws = xs + XTILE_F;

#pragma unroll
        for (int ks = 0; ks < 4; ks++) {
            const int kk = ks * 8;
            unsigned a[MT][4], b[NT][2];
#pragma unroll
            for (int mt = 0; mt < MT; mt++) {
                int rb = warp_m * (BM / 2) + mt * 16;
                a[mt][0] = __float_as_uint(xs[(rb + g    ) * GP + kk + tg    ]);
                a[mt][1] = __float_as_uint(xs[(rb + g + 8) * GP + kk + tg    ]);
                a[mt][2] = __float_as_uint(xs[(rb + g    ) * GP + kk + tg + 4]);
                a[mt][3] = __float_as_uint(xs[(rb + g + 8) * GP + kk + tg + 4]);
            }
#pragma unroll
            for (int nt = 0; nt < NT; nt++) {
                int nb = warp_n * (BN / 4) + nt * 8 + g;
                b[nt][0] = __float_as_uint(ws[nb * GP + kk + tg    ]);
                b[nt][1] = __float_as_uint(ws[nb * GP + kk + tg + 4]);
            }
#pragma unroll
            for (int mt = 0; mt < MT; mt++)
#pragma unroll
                for (int nt = 0; nt < NT; nt++)
                    MMA_TF32(c[mt][nt], a[mt][0], a[mt][1], a[mt][2], a[mt][3],
                             b[nt][0], b[nt][1]);
        }
    }

#pragma unroll
    for (int mt = 0; mt < MT; mt++) {
#pragma unroll
        for (int nt = 0; nt < NT; nt++) {
            int col = n0 + warp_n * (BN / 4) + nt * 8 + 2 * tg;
            float b0 = bias[col], b1 = bias[col + 1];
            int r0 = m0 + warp_m * (BM / 2) + mt * 16 + g;
            float v0 = c[mt][nt][0] + b0;
            float v1 = c[mt][nt][1] + b1;
            float v2 = c[mt][nt][2] + b0;
            float v3 = c[mt][nt][3] + b1;
            if (relu) {
                v0 = fmaxf(v0, 0.f); v1 = fmaxf(v1, 0.f);
                v2 = fmaxf(v2, 0.f); v3 = fmaxf(v3, 0.f);
            }
            Y[(size_t)r0 * N + col]           = v0;
            Y[(size_t)r0 * N + col + 1]       = v1;
            Y[(size_t)(r0 + 8) * N + col]     = v2;
            Y[(size_t)(r0 + 8) * N + col + 1] = v3;
        }
    }
}

#define SMEMB(BM,BN) (2 * ((BM) + (BN)) * GP * 4)

// ---------------- residual + LayerNorm (row = 256) --------------------------
__global__ void add_ln_kernel(const float* __restrict__ A, const float* __restrict__ Bv,
                              const float* __restrict__ g, const float* __restrict__ be,
                              const float* __restrict__ qpos,
                              float* __restrict__ Y, float* __restrict__ Yq)
{
    int row = blockIdx.x, t = threadIdx.x;
    float x = A[(size_t)row * Cc + t] + Bv[(size_t)row * Cc + t];
    float s = x, s2 = x * x;
#pragma unroll
    for (int o = 16; o > 0; o >>= 1) {
        s  += __shfl_xor_sync(0xffffffffu, s, o);
        s2 += __shfl_xor_sync(0xffffffffu, s2, o);
    }
    __shared__ float ss[8], ss2[8];
    int w = t >> 5;
    if ((t & 31) == 0) { ss[w] = s; ss2[w] = s2; }
    __syncthreads();
    s = 0.f; s2 = 0.f;
#pragma unroll
    for (int i = 0; i < 8; i++) { s += ss[i]; s2 += ss2[i]; }
    float mean = s * (1.f / Cc);
    float var  = s2 * (1.f / Cc) - mean * mean;
    float inv  = rsqrtf(var + 1e-5f);
    float y = (x - mean) * inv * g[t] + be[t];
    Y[(size_t)row * Cc + t] = y;
    if (qpos) Yq[(size_t)row * Cc + t] = y + qpos[(size_t)row * Cc + t];
}

// residual + 4 split-K partials + LayerNorm
__global__ void add_ln4_kernel(const float* __restrict__ A, const float* __restrict__ P,
                               const float* __restrict__ g, const float* __restrict__ be,
                               float* __restrict__ Y)
{
    int row = blockIdx.x, t = threadIdx.x;
    size_t idx = (size_t)row * Cc + t;
    float x = A[idx] + P[idx] + P[idx + (size_t)MROWS*Cc]
            + P[idx + (size_t)2*MROWS*Cc] + P[idx + (size_t)3*MROWS*Cc];
    float s = x, s2 = x * x;
#pragma unroll
    for (int o = 16; o > 0; o >>= 1) {
        s  += __shfl_xor_sync(0xffffffffu, s, o);
        s2 += __shfl_xor_sync(0xffffffffu, s2, o);
    }
    __shared__ float ss[8], ss2[8];
    int w = t >> 5;
    if ((t & 31) == 0) { ss[w] = s; ss2[w] = s2; }
    __syncthreads();
    s = 0.f; s2 = 0.f;
#pragma unroll
    for (int i = 0; i < 8; i++) { s += ss[i]; s2 += ss2[i]; }
    float mean = s * (1.f / Cc);
    float var  = s2 * (1.f / Cc) - mean * mean;
    float inv  = rsqrtf(var + 1e-5f);
    Y[idx] = (x - mean) * inv * g[t] + be[t];
}

// ---------------- tensor-core flash attention -------------------------------
#define KP 36
#define VP 68
__global__ __launch_bounds__(256, 2)
void attn_kernel(const float* __restrict__ Q, const float* __restrict__ K,
                 const float* __restrict__ V, float* __restrict__ O)
{
    __shared__ float Qs[128 * KP];
    __shared__ float Ks[64 * KP];
    __shared__ float Vt[32 * VP];

    const int t = threadIdx.x;
    const int warp = t >> 5, lane = t & 31;
    const int g = lane >> 2, tg = lane & 3;
    const int bh = blockIdx.y;
    const int b = bh >> 3, h = bh & 7;
    const int q0 = blockIdx.x * 128;
    const size_t base = ((size_t)b * LQ) * Cc + h * DH;

#pragma unroll
    for (int j = 0; j < 4; j++) {
        int idx = j * 256 + t;
        int row = idx >> 3, c4 = (idx & 7) * 4;
        float4 v4 = *(const float4*)&Q[base + (size_t)(q0 + row) * Cc + c4];
        v4.x *= 0.17677669529663687f; v4.y *= 0.17677669529663687f;
        v4.z *= 0.17677669529663687f; v4.w *= 0.17677669529663687f;
        *(float4*)&Qs[row * KP + c4] = v4;
    }
    __syncthreads();

    unsigned qa[4][4];
    {
        int r = warp * 16 + g;
#pragma unroll
        for (int kt = 0; kt < 4; kt++) {
            qa[kt][0] = __float_as_uint(Qs[r * KP + kt * 8 + tg]);
            qa[kt][1] = __float_as_uint(Qs[(r + 8) * KP + kt * 8 + tg]);
            qa[kt][2] = __float_as_uint(Qs[r * KP + kt * 8 + tg + 4]);
            qa[kt][3] = __float_as_uint(Qs[(r + 8) * KP + kt * 8 + tg + 4]);
        }
    }

    float o[4][4];
#pragma unroll
    for (int nt = 0; nt < 4; nt++)
#pragma unroll
        for (int r = 0; r < 4; r++) o[nt][r] = 0.f;
    float m0 = -1e30f, m1 = -1e30f, l0 = 0.f, l1 = 0.f;

    for (int c0 = 0; c0 < LQ; c0 += 64) {
        __syncthreads();
#pragma unroll
        for (int j = 0; j < 2; j++) {
            int idx = j * 256 + t;
            int row = idx >> 3, c4 = (idx & 7) * 4;
            *(float4*)&Ks[row * KP + c4] =
                *(const float4*)&K[base + (size_t)(c0 + row) * Cc + c4];
        }
        {
            int key = t & 63, dg = t >> 6;
#pragma unroll
            for (int jj = 0; jj < 2; jj++) {
                float4 v4 = *(const float4*)&V[base + (size_t)(c0 + key) * Cc + dg * 8 + jj * 4];
                Vt[(dg * 8 + jj * 4 + 0) * VP + key] = __uint_as_float(rna_tf32(v4.x));
                Vt[(dg * 8 + jj * 4 + 1) * VP + key] = __uint_as_float(rna_tf32(v4.y));
                Vt[(dg * 8 + jj * 4 + 2) * VP + key] = __uint_as_float(rna_tf32(v4.z));
                Vt[(dg * 8 + jj * 4 + 3) * VP + key] = __uint_as_float(rna_tf32(v4.w));
            }
        }
        __syncthreads();

        float c[8][4];
#pragma unroll
        for (int nt = 0; nt < 8; nt++)
#pragma unroll
            for (int r = 0; r < 4; r++) c[nt][r] = 0.f;
#pragma unroll
        for (int kt = 0; kt < 4; kt++) {
#pragma unroll
            for (int nt = 0; nt < 8; nt++) {
                unsigned b0 = __float_as_uint(Ks[(nt * 8 + g) * KP + kt * 8 + tg]);
                unsigned b1 = __float_as_uint(Ks[(nt * 8 + g) * KP + kt * 8 + tg + 4]);
                MMA_TF32(c[nt], qa[kt][0], qa[kt][1], qa[kt][2], qa[kt][3], b0, b1);
            }
        }

        float mx0 = -1e30f, mx1 = -1e30f;
#pragma unroll
        for (int nt = 0; nt < 8; nt++) {
            mx0 = fmaxf(mx0, fmaxf(c[nt][0], c[nt][1]));
            mx1 = fmaxf(mx1, fmaxf(c[nt][2], c[nt][3]));
        }
        mx0 = fmaxf(mx0, __shfl_xor_sync(0xffffffffu, mx0, 1));
        mx0 = fmaxf(mx0, __shfl_xor_sync(0xffffffffu, mx0, 2));
        mx1 = fmaxf(mx1, __shfl_xor_sync(0xffffffffu, mx1, 1));
        mx1 = fmaxf(mx1, __shfl_xor_sync(0xffffffffu, mx1, 2));
        float mn0 = fmaxf(m0, mx0), mn1 = fmaxf(m1, mx1);
        float cor0 = __expf(m0 - mn0), cor1 = __expf(m1 - mn1);
        l0 *= cor0; l1 *= cor1;
#pragma unroll
        for (int nt = 0; nt < 4; nt++) {
            o[nt][0] *= cor0; o[nt][1] *= cor0;
            o[nt][2] *= cor1; o[nt][3] *= cor1;
        }
#pragma unroll
        for (int nt = 0; nt < 8; nt++) {
            float p0 = __expf(c[nt][0] - mn0);
            float p1 = __expf(c[nt][1] - mn0);
            float p2 = __expf(c[nt][2] - mn1);
            float p3 = __expf(c[nt][3] - mn1);
            l0 += p0 + p1; l1 += p2 + p3;
            c[nt][0] = __uint_as_float(rna_tf32(p0));
            c[nt][1] = __uint_as_float(rna_tf32(p1));
            c[nt][2] = __uint_as_float(rna_tf32(p2));
            c[nt][3] = __uint_as_float(rna_tf32(p3));
        }
        m0 = mn0; m1 = mn1;

        const int src0 = (lane & ~3) | (tg >> 1);
        const int src2 = src0 + 2;
        const bool odd = tg & 1;
#pragma unroll
        for (int kt = 0; kt < 8; kt++) {
            float e00 = __shfl_sync(0xffffffffu, c[kt][0], src0);
            float e01 = __shfl_sync(0xffffffffu, c[kt][1], src0);
            float e10 = __shfl_sync(0xffffffffu, c[kt][2], src0);
            float e11 = __shfl_sync(0xffffffffu, c[kt][3], src0);
            float e20 = __shfl_sync(0xffffffffu, c[kt][0], src2);
            float e21 = __shfl_sync(0xffffffffu, c[kt][1], src2);
            float e30 = __shfl_sync(0xffffffffu, c[kt][2], src2);
            float e31 = __shfl_sync(0xffffffffu, c[kt][3], src2);
            unsigned a0 = __float_as_uint(odd ? e01 : e00);
            unsigned a1 = __float_as_uint(odd ? e11 : e10);
            unsigned a2 = __float_as_uint(odd ? e21 : e20);
            unsigned a3 = __float_as_uint(odd ? e31 : e30);
#pragma unroll
            for (int nt = 0; nt < 4; nt++) {
                unsigned b0 = __float_as_uint(Vt[(nt * 8 + g) * VP + kt * 8 + tg]);
                unsigned b1 = __float_as_uint(Vt[(nt * 8 + g) * VP + kt * 8 + tg + 4]);
                MMA_TF32(o[nt], a0, a1, a2, a3, b0, b1);
            }
        }
    }

    l0 += __shfl_xor_sync(0xffffffffu, l0, 1);
    l0 += __shfl_xor_sync(0xffffffffu, l0, 2);
    l1 += __shfl_xor_sync(0xffffffffu, l1, 1);
    l1 += __shfl_xor_sync(0xffffffffu, l1, 2);
    float inv0 = 1.f / l0, inv1 = 1.f / l1;

    int r0 = q0 + warp * 16 + g;
#pragma unroll
    for (int nt = 0; nt < 4; nt++) {
        int col = nt * 8 + 2 * tg;
        float2 w0 = make_float2(o[nt][0] * inv0, o[nt][1] * inv0);
        float2 w1 = make_float2(o[nt][2] * inv1, o[nt][3] * inv1);
        *(float2*)&O[base + (size_t)r0 * Cc + col]       = w0;
        *(float2*)&O[base + (size_t)(r0 + 8) * Cc + col] = w1;
    }
}

// ---------------- deformable sampling (warp per (b,q,h), lane = channel) ----
__global__ void deform_kernel(const float* __restrict__ val, const float* __restrict__ offs,
                              const float* __restrict__ awl, const float* __restrict__ ref,
                              float* __restrict__ out)
{
    const int gid  = blockIdx.x * 4 + (threadIdx.x >> 5);
    const int lane = threadIdx.x & 31;
    const int h   = gid & 7;
    const int row = gid >> 3;
    const int b   = row >> 10;

    float a[16];
    float mx = -1e30f;
#pragma unroll
    for (int i = 0; i < 16; i++) {
        a[i] = awl[(size_t)row * 128 + h * 16 + i];
        mx = fmaxf(mx, a[i]);
    }
    float ssum = 0.f;
#pragma unroll
    for (int i = 0; i < 16; i++) { a[i] = __expf(a[i] - mx); ssum += a[i]; }
    float invs = 1.f / ssum;

    const int starts[4] = {0, 16384, 20480, 21504};
    float acc = 0.f;
#pragma unroll
    for (int lvl = 0; lvl < 4; lvl++) {
        const int Wl = 128 >> lvl;
        const int Hl = 128 >> lvl;
        const int start = starts[lvl];
        float rx = ref[((size_t)row * 4 + lvl) * 2 + 0];
        float ry = ref[((size_t)row * 4 + lvl) * 2 + 1];
#pragma unroll
        for (int p = 0; p < 4; p++) {
            size_t obase = (size_t)row * 256 + (((h * 4 + lvl) * 4 + p) * 2);
            float ox = offs[obase + 0];
            float oy = offs[obase + 1];
            float x = rx * (float)Wl + ox - 0.5f;
            float y = ry * (float)Hl + oy - 0.5f;
            float xf = floorf(x), yf = floorf(y);
            int x0 = (int)xf, y0 = (int)yf;
            float wx1 = x - xf, wx0 = 1.f - wx1;
            float wy1 = y - yf, wy0 = 1.f - wy1;
            float aw = a[lvl * 4 + p] * invs;

            float w00 = wx0 * wy0 * aw, w10 = wx1 * wy0 * aw;
            float w01 = wx0 * wy1 * aw, w11 = wx1 * wy1 * aw;
#pragma unroll
            for (int cidx = 0; cidx < 4; cidx++) {
                int ix = x0 + (cidx & 1);
                int iy = y0 + (cidx >> 1);
                float w = (cidx == 0) ? w00 : (cidx == 1) ? w10 : (cidx == 2) ? w01 : w11;
                if (ix >= 0 && ix < Wl && iy >= 0 && iy < Hl) {
                    size_t idx = (size_t)(b * LSRC + start + iy * Wl + ix) * Cc + h * DH + lane;
                    acc += w * val[idx];
                }
            }
        }
    }
    out[(size_t)row * Cc + h * DH + lane] = acc;
}

// ---------------- launcher ---------------------------------------------------
extern "C" void kernel_launch(void* const* d_in, const int* in_sizes, int n_in,
                              void* d_out, int out_size)
{
    const float* tgt   = (const float*)d_in[0];
    const float* qpos  = (const float*)d_in[1];
    const float* refp  = (const float*)d_in[2];
    const float* src   = (const float*)d_in[3];
    const float* in_w  = (const float*)d_in[4];
    const float* in_b  = (const float*)d_in[5];
    const float* sa_w  = (const float*)d_in[6];
    const float* sa_b  = (const float*)d_in[7];
    const float* off_w = (const float*)d_in[8];
    const float* off_b = (const float*)d_in[9];
    const float* aw_w  = (const float*)d_in[10];
    const float* aw_b  = (const float*)d_in[11];
    const float* val_w = (const float*)d_in[12];
    const float* val_b = (const float*)d_in[13];
    const float* co_w  = (const float*)d_in[14];
    const float* co_b  = (const float*)d_in[15];
    const float* ln1_g = (const float*)d_in[16];
    const float* ln1_b = (const float*)d_in[17];
    const float* ln2_g = (const float*)d_in[18];
    const float* ln2_b = (const float*)d_in[19];
    const float* ln3_g = (const float*)d_in[20];
    const float* ln3_b = (const float*)d_in[21];
    const float* f1_w  = (const float*)d_in[22];
    const float* f1_b  = (const float*)d_in[23];
    const float* f2_w  = (const float*)d_in[24];
    const float* f2_b  = (const float*)d_in[25];
    float* out = (float*)d_out;

    float *qk, *qk2, *qkv, *attn, *tmp, *t1, *t2, *off, *aw, *val, *ffn, *part, *zero;
    cudaGetSymbolAddress((void**)&qk,   g_qk);
    cudaGetSymbolAddress((void**)&qk2,  g_qk2);
    cudaGetSymbolAddress((void**)&qkv,  g_qkv);
    cudaGetSymbolAddress((void**)&attn, g_attn);
    cudaGetSymbolAddress((void**)&tmp,  g_tmp);
    cudaGetSymbolAddress((void**)&t1,   g_tgt1);
    cudaGetSymbolAddress((void**)&t2,   g_tgt2);
    cudaGetSymbolAddress((void**)&off,  g_off);
    cudaGetSymbolAddress((void**)&aw,   g_aw);
    cudaGetSymbolAddress((void**)&val,  g_val);
    cudaGetSymbolAddress((void**)&ffn,  g_ffn);
    cudaGetSymbolAddress((void**)&part, g_part);
    cudaGetSymbolAddress((void**)&zero, g_zero);

    static cudaStream_t s1;
    static cudaEvent_t evFork, evJoin;
    static int inited = 0;
    if (!inited) {
        cudaStreamCreateWithFlags(&s1, cudaStreamNonBlocking);
        cudaEventCreateWithFlags(&evFork, cudaEventDisableTiming);
        cudaEventCreateWithFlags(&evJoin, cudaEventDisableTiming);
        cudaFuncSetAttribute(gemm_tc<256,64,64>,
                             cudaFuncAttributeMaxDynamicSharedMemorySize, SMEMB(64,64));
        cudaFuncSetAttribute(gemm_tc<256,128,64>,
                             cudaFuncAttributeMaxDynamicSharedMemorySize, SMEMB(128,64));
        cudaFuncSetAttribute(gemm_tc<256,128,128>,
                             cudaFuncAttributeMaxDynamicSharedMemorySize, SMEMB(128,128));
        inited = 1;
    }

    const int NTOT = MROWS * Cc;

    // 1) qk = tgt + query_pos
    add_kernel<<<(NTOT + 255) / 256, 256>>>(tgt, qpos, qk, NTOT);

    // fork: value projection on side stream (depends only on src)
    cudaEventRecord(evFork, 0);
    cudaStreamWaitEvent(s1, evFork, 0);
    gemm_tc<256,128,128><<<dim3(2, VROWS / 128), 256, SMEMB(128,128), s1>>>(
        src, nullptr, val_w, val_b, val, VROWS, Cc, 0, 0,
        nullptr, nullptr, nullptr, 0, 256, 256);
    cudaEventRecord(evJoin, s1);

    // 2) Q/K/V projections — batched over grid.z
    gemm_tc<256,64,64><<<dim3(4, 64, 3), 256, SMEMB(64,64)>>>(
        qk, tgt, in_w, in_b, qkv, MROWS, Cc, 0, 1,
        nullptr, nullptr, nullptr, 0, 256, 256);

    // 3) attention (tensor-core flash)
    attn_kernel<<<dim3(LQ / 128, Bz * Hh), 256>>>(
        qkv, qkv + MROWS * Cc, qkv + 2 * MROWS * Cc, attn);

    // 4) self-attn out proj + residual + LN(ln2) -> t1, and qk2 = t1 + qpos
    gemm_tc<256,64,64><<<dim3(4, 64), 256, SMEMB(64,64)>>>(
        attn, nullptr, sa_w, sa_b, tmp, MROWS, Cc, 0, 0,
        nullptr, nullptr, nullptr, 0, 256, 256);
    add_ln_kernel<<<MROWS, 256>>>(tgt, tmp, ln2_g, ln2_b, qpos, t1, qk2);

    // 5+6) offsets + attention weights in one z-batched launch
    gemm_tc<256,64,64><<<dim3(4, 64, 2), 256, SMEMB(64,64)>>>(
        qk2, nullptr, off_w, off_b, off, MROWS, Cc, 0, 2,
        aw_w, aw_b, aw, 128, 256, 256);

    // join value projection, then deformable sampling
    cudaStreamWaitEvent(0, evJoin, 0);
    deform_kernel<<<(MROWS * Hh) / 4, 128>>>(val, off, aw, refp, attn);

    // 8) co proj + residual + LN(ln1) -> t2
    gemm_tc<256,64,64><<<dim3(4, 64), 256, SMEMB(64,64)>>>(
        attn, nullptr, co_w, co_b, tmp, MROWS, Cc, 0, 0,
        nullptr, nullptr, nullptr, 0, 256, 256);
    add_ln_kernel<<<MROWS, 256>>>(t1, tmp, ln1_g, ln1_b, nullptr, t2, nullptr);

    // 9) FFN: f1 (relu), f2 split-K over z=4, fused reduce+LN
    gemm_tc<256,128,64><<<dim3(16, 32), 256, SMEMB(128,64)>>>(
        t2, nullptr, f1_w, f1_b, ffn, MROWS, DFF, 1, 0,
        nullptr, nullptr, nullptr, 0, 256, 256);
    gemm_tc<256,64,64><<<dim3(4, 64, 4), 256, SMEMB(64,64)>>>(
        ffn, nullptr, f2_w, f2_b, part, MROWS, Cc, 0, 3,
        nullptr, zero, nullptr, 0, 1024, 1024);
    add_ln4_kernel<<<MROWS, 256>>>(t2, part, ln3_g, ln3_b, out);
}